// round 13
// baseline (speedup 1.0000x reference)
#include <cuda_runtime.h>
#include <cuda_fp16.h>
#include <math.h>

#define NN    10000
#define EIN   160000
#define ETOT  170000
#define NHEAD 8
#define HID   256
#define KBIG  (NHEAD * HID)   // 2048
#define EPSI  1e-5f
#define SLOPE 0.2f

typedef unsigned long long ull;

// ---------------- scratch ----------------
__device__ float  d_h0[NN * HID];
__device__ float  d_hin[NN * HID];
__device__ __half d_xh[NN * HID];
__device__ __half d_w0h[HID * HID];
__device__ __half d_aggh[NN * KBIG];
__device__ __half d_w1h[KBIG * HID];
__device__ float  d_part[4 * NN * HID];
__device__ float  d_out0[NN * HID];
__device__ float  d_out1[NN * HID];
__device__ float  d_h2[NN * HID];
__device__ float  d_ss[NN * NHEAD];
__device__ float  d_sd[NN * NHEAD];
__device__ float  d_wsrc[NHEAD * HID];
__device__ float  d_wdst[NHEAD * HID];
__device__ int    d_counts[NN + 1];
__device__ int    d_offsets[NN + 1];
__device__ int    d_cursor[NN];
__device__ int    d_srcs[ETOT];
__device__ float  d_alpha[ETOT * NHEAD];
__device__ float  d_bnstat[4 * HID];

// ---------------- CSR build (count also zeroes cursor + bnstat) ----------------
__global__ void count_kernel(const int* __restrict__ dst) {
    int i = blockIdx.x * blockDim.x + threadIdx.x;
    if (i < NN) d_cursor[i] = 0;
    if (i < 4 * HID) d_bnstat[i] = 0.f;
    if (i >= ETOT) return;
    int d = (i < EIN) ? dst[i] : (i - EIN);
    atomicAdd(&d_counts[d], 1);
}

__global__ void scan_kernel() {
    __shared__ int sums[1024];
    const int n = NN;
    const int chunk = (n + 1023) / 1024;
    int tid = threadIdx.x;
    int start = tid * chunk;
    int local = 0;
    for (int i = 0; i < chunk; i++)
        if (start + i < n) local += d_counts[start + i];
    sums[tid] = local;
    __syncthreads();
    for (int off = 1; off < 1024; off <<= 1) {
        int v = (tid >= off) ? sums[tid - off] : 0;
        __syncthreads();
        sums[tid] += v;
        __syncthreads();
    }
    int run = (tid == 0) ? 0 : sums[tid - 1];
    for (int i = 0; i < chunk; i++) {
        if (start + i < n) {
            d_offsets[start + i] = run;
            run += d_counts[start + i];
        }
    }
    if (tid == 1023) d_offsets[n] = sums[1023];
}

__global__ void place_kernel(const int* __restrict__ src, const int* __restrict__ dst) {
    int i = blockIdx.x * blockDim.x + threadIdx.x;
    if (i >= ETOT) return;
    int s, d;
    if (i < EIN) { s = src[i]; d = dst[i]; }
    else         { s = d = i - EIN; }
    int pos = d_offsets[d] + atomicAdd(&d_cursor[d], 1);
    d_srcs[pos] = s;
}

// ---------------- prep: conv x/W0 to half + W1 permute-to-half + wtilde ----------------
#define PREP_N1 ((NN * HID + HID * HID) / 4)   // float4 convert items
#define PREP_N2 (KBIG * (HID / 2))             // w1h half2 items
#define PREP_N3 (NHEAD * HID * 32)             // wtilde: warp per output
__global__ void prep_kernel(const float* __restrict__ x, const float* __restrict__ W0,
                            const float* __restrict__ W1,
                            const float* __restrict__ as1, const float* __restrict__ ad1) {
    int i = blockIdx.x * blockDim.x + threadIdx.x;
    const int nx = NN * HID / 4;
    if (i < PREP_N1) {
        if (i < nx) {
            const float4 v = ((const float4*)x)[i];
            ((__half2*)d_xh)[i * 2]     = __floats2half2_rn(v.x, v.y);
            ((__half2*)d_xh)[i * 2 + 1] = __floats2half2_rn(v.z, v.w);
        } else {
            int j = i - nx;
            const float4 v = ((const float4*)W0)[j];
            ((__half2*)d_w0h)[j * 2]     = __floats2half2_rn(v.x, v.y);
            ((__half2*)d_w0h)[j * 2 + 1] = __floats2half2_rn(v.z, v.w);
        }
    } else if (i < PREP_N1 + PREP_N2) {
        int j = i - PREP_N1;
        int r = j >> 7;
        int c2 = (j & 127) * 2;
        const float* src = W1 + (size_t)(r & 255) * KBIG + (r >> 8) * HID + c2;
        *(__half2*)&d_w1h[(size_t)r * HID + c2] = __floats2half2_rn(src[0], src[1]);
    } else if (i < PREP_N1 + PREP_N2 + PREP_N3) {
        int j = i - PREP_N1 - PREP_N2;       // PREP_N1+PREP_N2 divisible by 32
        int w = j >> 5;
        int lane = j & 31;
        int h = w >> 8;
        int k = w & 255;
        const float* wrow = W1 + (size_t)k * KBIG + h * HID;
        const float* ar = as1 + h * HID;
        const float* dr = ad1 + h * HID;
        float s = 0.f, d = 0.f;
        for (int c = lane; c < HID; c += 32) {
            float wv = wrow[c];
            s = fmaf(wv, ar[c], s);
            d = fmaf(wv, dr[c], d);
        }
        #pragma unroll
        for (int o = 16; o > 0; o >>= 1) {
            s += __shfl_xor_sync(0xffffffffu, s, o);
            d += __shfl_xor_sync(0xffffffffu, d, o);
        }
        if (lane == 0) {
            d_wsrc[w] = s;
            d_wdst[w] = d;
        }
    }
}

// ---------------- warp-level per-node softmax (called by warp 0 of node block) ----------------
__device__ __forceinline__ void node_softmax(int nod, int lane) {
    int beg = d_offsets[nod], end = d_offsets[nod + 1];
    const float4* ss4 = (const float4*)d_ss;
    float4* al4 = (float4*)d_alpha;

    float sd[NHEAD];
    #pragma unroll
    for (int h = 0; h < NHEAD; h++) sd[h] = d_sd[nod * NHEAD + h];

    float mx[NHEAD];
    #pragma unroll
    for (int h = 0; h < NHEAD; h++) mx[h] = -1e30f;
    for (int p = beg + lane; p < end; p += 32) {
        int s = d_srcs[p];
        float4 v0 = ss4[s * 2], v1 = ss4[s * 2 + 1];
        float sv[NHEAD] = {v0.x, v0.y, v0.z, v0.w, v1.x, v1.y, v1.z, v1.w};
        #pragma unroll
        for (int h = 0; h < NHEAD; h++) {
            float sc = sv[h] + sd[h];
            sc = (sc >= 0.f) ? sc : SLOPE * sc;
            mx[h] = fmaxf(mx[h], sc);
        }
    }
    #pragma unroll
    for (int h = 0; h < NHEAD; h++)
        #pragma unroll
        for (int o = 16; o > 0; o >>= 1)
            mx[h] = fmaxf(mx[h], __shfl_xor_sync(0xffffffffu, mx[h], o));

    float sum[NHEAD];
    #pragma unroll
    for (int h = 0; h < NHEAD; h++) sum[h] = 0.f;
    for (int p = beg + lane; p < end; p += 32) {
        int s = d_srcs[p];
        float4 v0 = ss4[s * 2], v1 = ss4[s * 2 + 1];
        float sv[NHEAD] = {v0.x, v0.y, v0.z, v0.w, v1.x, v1.y, v1.z, v1.w};
        float ev[NHEAD];
        #pragma unroll
        for (int h = 0; h < NHEAD; h++) {
            float sc = sv[h] + sd[h];
            sc = (sc >= 0.f) ? sc : SLOPE * sc;
            float e = __expf(sc - mx[h]);
            sum[h] += e;
            ev[h] = e;
        }
        al4[p * 2]     = make_float4(ev[0], ev[1], ev[2], ev[3]);
        al4[p * 2 + 1] = make_float4(ev[4], ev[5], ev[6], ev[7]);
    }
    #pragma unroll
    for (int h = 0; h < NHEAD; h++)
        #pragma unroll
        for (int o = 16; o > 0; o >>= 1)
            sum[h] += __shfl_xor_sync(0xffffffffu, sum[h], o);

    float r[NHEAD];
    #pragma unroll
    for (int h = 0; h < NHEAD; h++) r[h] = 1.f / sum[h];

    for (int p = beg + lane; p < end; p += 32) {
        float4 e0 = al4[p * 2], e1 = al4[p * 2 + 1];
        e0.x *= r[0]; e0.y *= r[1]; e0.z *= r[2]; e0.w *= r[3];
        e1.x *= r[4]; e1.y *= r[5]; e1.z *= r[6]; e1.w *= r[7];
        al4[p * 2]     = e0;
        al4[p * 2 + 1] = e1;
    }
}

// ---------------- fused softmax + layer-0 aggregation ----------------
__global__ void softagg0(const float* __restrict__ h,
                         const float* __restrict__ bias,
                         float* __restrict__ out) {
    int nod = blockIdx.x;
    int t = threadIdx.x;
    if (t < 32) node_softmax(nod, t);
    __syncthreads();
    int head = t >> 5;
    int beg = d_offsets[nod], end = d_offsets[nod + 1];
    float acc = 0.f;
    int p = beg;
    for (; p + 2 <= end; p += 2) {
        int s0 = d_srcs[p], s1 = d_srcs[p + 1];
        float a0 = d_alpha[p * NHEAD + head];
        float a1 = d_alpha[(p + 1) * NHEAD + head];
        float v0 = h[(size_t)s0 * HID + t];
        float v1 = h[(size_t)s1 * HID + t];
        acc = fmaf(v0, a0, acc);
        acc = fmaf(v1, a1, acc);
    }
    if (p < end) {
        float a = d_alpha[p * NHEAD + head];
        acc = fmaf(h[(size_t)d_srcs[p] * HID + t], a, acc);
    }
    out[(size_t)nod * HID + t] = acc + bias[t];
}

// ---------------- fused softmax + layer-1 aggregation ----------------
__global__ void softagg8(const float* __restrict__ hin) {
    int nod = blockIdx.x;
    int t = threadIdx.x;
    if (t < 32) node_softmax(nod, t);
    __syncthreads();
    int beg = d_offsets[nod], end = d_offsets[nod + 1];
    const float4* al4 = (const float4*)d_alpha;
    float acc[NHEAD];
    #pragma unroll
    for (int i = 0; i < NHEAD; i++) acc[i] = 0.f;
    int p = beg;
    for (; p + 2 <= end; p += 2) {
        int s0 = d_srcs[p], s1 = d_srcs[p + 1];
        float v0 = hin[(size_t)s0 * HID + t];
        float v1 = hin[(size_t)s1 * HID + t];
        float4 a00 = al4[p * 2], a01 = al4[p * 2 + 1];
        float4 a10 = al4[p * 2 + 2], a11 = al4[p * 2 + 3];
        float l0[NHEAD] = {a00.x, a00.y, a00.z, a00.w, a01.x, a01.y, a01.z, a01.w};
        float l1[NHEAD] = {a10.x, a10.y, a10.z, a10.w, a11.x, a11.y, a11.z, a11.w};
        #pragma unroll
        for (int i = 0; i < NHEAD; i++) {
            acc[i] = fmaf(v0, l0[i], acc[i]);
            acc[i] = fmaf(v1, l1[i], acc[i]);
        }
    }
    if (p < end) {
        int s = d_srcs[p];
        float v = hin[(size_t)s * HID + t];
        float4 a0 = al4[p * 2], a1 = al4[p * 2 + 1];
        float al[NHEAD] = {a0.x, a0.y, a0.z, a0.w, a1.x, a1.y, a1.z, a1.w};
        #pragma unroll
        for (int i = 0; i < NHEAD; i++) acc[i] = fmaf(v, al[i], acc[i]);
    }
    __half* op = d_aggh + (size_t)nod * KBIG + t;
    #pragma unroll
    for (int i = 0; i < NHEAD; i++) op[i * HID] = __float2half_rn(acc[i]);
}

// ---------------- batch norm ----------------
__global__ void bn_partial(const float* __restrict__ x, int statoff) {
    int c = threadIdx.x;
    int nb = gridDim.x;
    int rows = (NN + nb - 1) / nb;
    int r0 = blockIdx.x * rows;
    int r1 = min(NN, r0 + rows);
    float s = 0.f, s2 = 0.f;
    for (int r = r0; r < r1; r++) {
        float v = x[(size_t)r * HID + c];
        s += v; s2 += v * v;
    }
    atomicAdd(&d_bnstat[statoff + c], s);
    atomicAdd(&d_bnstat[statoff + c + HID], s2);
}

__device__ __forceinline__ void bn_coeff(int statoff, int c, float& mu, float& rinv) {
    float m = d_bnstat[statoff + c] * (1.f / NN);
    float v = d_bnstat[statoff + c + HID] * (1.f / NN) - m * m;
    mu = m;
    rinv = rsqrtf(v + EPSI);
}

__global__ void bn_apply(const float* __restrict__ x,
                         const float* __restrict__ g,
                         const float* __restrict__ be,
                         const float* __restrict__ resid,
                         float* __restrict__ out, int statoff) {
    int i = blockIdx.x * blockDim.x + threadIdx.x;
    if (i >= NN * HID) return;
    int c = i & (HID - 1);
    float mu, rinv;
    bn_coeff(statoff, c, mu, rinv);
    float v = g[c] * (x[i] - mu) * rinv + be[c];
    v = (v > 0.f) ? v : (expf(v) - 1.f);
    if (resid) v += resid[i];
    out[i] = v;
}

__global__ void bn_apply_scores(const float* __restrict__ x,
                                const float* __restrict__ g,
                                const float* __restrict__ be,
                                float* __restrict__ out, int statoff) {
    __shared__ float srow[HID];
    int row = blockIdx.x;
    int t = threadIdx.x;
    int i = row * HID + t;
    float mu, rinv;
    bn_coeff(statoff, t, mu, rinv);
    float v = g[t] * (x[i] - mu) * rinv + be[t];
    v = (v > 0.f) ? v : (expf(v) - 1.f);
    out[i] = v;
    srow[t] = v;
    __syncthreads();
    int head = t >> 5, lane = t & 31;
    float as = 0.f, ad = 0.f;
    #pragma unroll
    for (int cc = 0; cc < HID / 32; cc++) {
        int c2 = cc * 32 + lane;
        float vv = srow[c2];
        as = fmaf(vv, d_wsrc[head * HID + c2], as);
        ad = fmaf(vv, d_wdst[head * HID + c2], ad);
    }
    #pragma unroll
    for (int o = 16; o > 0; o >>= 1) {
        as += __shfl_xor_sync(0xffffffffu, as, o);
        ad += __shfl_xor_sync(0xffffffffu, ad, o);
    }
    if (lane == 0) {
        d_ss[row * NHEAD + head] = as;
        d_sd[row * NHEAD + head] = ad;
    }
}

// ---------------- fp32 split-K GEMM (f32x2, exact; classifier only) ----------------
__global__ __launch_bounds__(256, 2) void gemm128s(const float* __restrict__ A,
                                                   const float* __restrict__ B,
                                                   float* __restrict__ Cpart,
                                                   int M, int Nc, int lda, int ksz) {
    __shared__ float As[2][8][132];
    __shared__ float Bs[2][8][132];

    const int tid  = threadIdx.x;
    const int row0 = blockIdx.y * 128;
    const int col0 = blockIdx.x * 128;
    const int k0   = blockIdx.z * ksz;

    const int arow = tid >> 1;
    const int akg  = (tid & 1) * 4;
    const int bkr  = tid >> 5;
    const int bc4  = (tid & 31) * 4;

    const int lane = tid & 31;
    const int warp = tid >> 5;
    const int m0 = (warp & 3) * 32 + (lane >> 3) * 4;
    const int n0 = (warp >> 2) * 64 + (lane & 7) * 4;

    const int gra = row0 + arow;
    const int gcb = col0 + bc4;

    ull acc[8][4];
    #pragma unroll
    for (int i = 0; i < 8; i++)
        #pragma unroll
        for (int j = 0; j < 4; j++) acc[i][j] = 0ull;

    float aL[4], bL[4];

    auto load_tile = [&](int kabs) {
        if (gra < M) {
            const float4 v = *(const float4*)&A[(size_t)gra * lda + kabs + akg];
            aL[0] = v.x; aL[1] = v.y; aL[2] = v.z; aL[3] = v.w;
        } else {
            aL[0] = aL[1] = aL[2] = aL[3] = 0.f;
        }
        const float* Brow = B + (size_t)(kabs + bkr) * Nc;
        if (gcb + 4 <= Nc) {
            const float4 v = *(const float4*)&Brow[gcb];
            bL[0] = v.x; bL[1] = v.y; bL[2] = v.z; bL[3] = v.w;
        } else {
            #pragma unroll
            for (int i = 0; i < 4; i++)
                bL[i] = (gcb + i < Nc) ? Brow[gcb + i] : 0.f;
        }
    };
    auto store_tile = [&](int buf) {
        #pragma unroll
        for (int i = 0; i < 4; i++) As[buf][akg + i][arow] = aL[i];
        *(float4*)&Bs[buf][bkr][bc4] = make_float4(bL[0], bL[1], bL[2], bL[3]);
    };

    load_tile(k0);
    store_tile(0);
    __syncthreads();

    const int ntiles = ksz >> 3;
    for (int t = 0; t < ntiles; t++) {
        const int buf = t & 1;
        if (t + 1 < ntiles) load_tile(k0 + ((t + 1) << 3));
        #pragma unroll
        for (int k = 0; k < 8; k++) {
            float a_f[8];
            *(float4*)&a_f[0] = *(const float4*)&As[buf][k][m0];
            *(float4*)&a_f[4] = *(const float4*)&As[buf][k][m0 + 16];
            float4 bv0 = *(const float4*)&Bs[buf][k][n0];
            float4 bv1 = *(const float4*)&Bs[buf][k][n0 + 32];
            ull b2[4];
            asm("mov.b64 %0, {%1, %2};" : "=l"(b2[0]) : "f"(bv0.x), "f"(bv0.y));
            asm("mov.b64 %0, {%1, %2};" : "=l"(b2[1]) : "f"(bv0.z), "f"(bv0.w));
            asm("mov.b64 %0, {%1, %2};" : "=l"(b2[2]) : "f"(bv1.x), "f"(bv1.y));
            asm("mov.b64 %0, {%1, %2};" : "=l"(b2[3]) : "f"(bv1.z), "f"(bv1.w));
            #pragma unroll
            for (int i = 0; i < 8; i++) {
                ull a2;
                asm("mov.b64 %0, {%1, %1};" : "=l"(a2) : "f"(a_f[i]));
                #pragma unroll
                for (int j = 0; j < 4; j++)
                    asm("fma.rn.f32x2 %0, %1, %2, %0;"
                        : "+l"(acc[i][j]) : "l"(a2), "l"(b2[j]));
            }
        }
        if (t + 1 < ntiles) {
            store_tile(buf ^ 1);
            __syncthreads();
        }
    }

    float* Cp = Cpart + (size_t)blockIdx.z * M * Nc;
    #pragma unroll
    for (int i = 0; i < 8; i++) {
        const int gm = row0 + ((i < 4) ? (m0 + i) : (m0 + 16 + i - 4));
        if (gm >= M) continue;
        float* Crow = Cp + (size_t)gm * Nc;
        #pragma unroll
        for (int jj = 0; jj < 2; jj++) {
            const int gn = col0 + n0 + jj * 32;
            float v[4];
            asm("mov.b64 {%0, %1}, %2;" : "=f"(v[0]), "=f"(v[1]) : "l"(acc[i][jj * 2]));
            asm("mov.b64 {%0, %1}, %2;" : "=f"(v[2]), "=f"(v[3]) : "l"(acc[i][jj * 2 + 1]));
            if (gn + 4 <= Nc) {
                *(float4*)&Crow[gn] = make_float4(v[0], v[1], v[2], v[3]);
            } else {
                #pragma unroll
                for (int j = 0; j < 4; j++)
                    if (gn + j < Nc) Crow[gn + j] = v[j];
            }
        }
    }
}

// ---------------- fp16 tensor-core GEMM: 3-stage cp.async + ldmatrix + m16n8k16 ----------------
#define GF16_A_STRIDE (128 * 40)
#define GF16_B_STRIDE (32 * 136)
#define GF16_SMEM ((3 * (GF16_A_STRIDE + GF16_B_STRIDE)) * (int)sizeof(__half))

__global__ __launch_bounds__(256, 2) void gemm_f16(const __half* __restrict__ A,
                                                   const __half* __restrict__ B,
                                                   float* __restrict__ Cpart,
                                                   int M, int Nc, int lda, int ksz) {
    extern __shared__ __half sm16[];
    __half* sA = sm16;
    __half* sB = sm16 + 3 * GF16_A_STRIDE;

    const int tid  = threadIdx.x;
    const int row0 = blockIdx.y * 128;
    const int col0 = blockIdx.x * 128;
    const int k0   = blockIdx.z * ksz;
    const int lane = tid & 31;
    const int warp = tid >> 5;
    const int wm   = (warp >> 2) * 64;
    const int wn   = (warp & 3) * 32;

    const int ar = tid >> 1;
    const int ac = (tid & 1) * 16;
    const int br = tid >> 3;
    const int bc = (tid & 7) * 16;

    float c[4][4][4];
    #pragma unroll
    for (int mi = 0; mi < 4; mi++)
        #pragma unroll
        for (int ni = 0; ni < 4; ni++)
            #pragma unroll
            for (int q = 0; q < 4; q++) c[mi][ni][q] = 0.f;

    auto load_stage = [&](int st, int kabs) {
        const __half* ag = A + (size_t)(row0 + ar) * lda + kabs + ac;
        int pa = (row0 + ar < M) ? 16 : 0;
        unsigned sa = (unsigned)__cvta_generic_to_shared(&sA[(st * 128 + ar) * 40 + ac]);
        asm volatile("cp.async.cg.shared.global [%0], [%1], 16, %2;\n" :: "r"(sa), "l"(ag), "r"(pa));
        asm volatile("cp.async.cg.shared.global [%0], [%1], 16, %2;\n" :: "r"(sa + 16), "l"(ag + 8), "r"(pa));
        const __half* bg = B + (size_t)(kabs + br) * Nc + col0 + bc;
        unsigned sb = (unsigned)__cvta_generic_to_shared(&sB[(st * 32 + br) * 136 + bc]);
        asm volatile("cp.async.cg.shared.global [%0], [%1], 16;\n" :: "r"(sb), "l"(bg));
        asm volatile("cp.async.cg.shared.global [%0], [%1], 16;\n" :: "r"(sb + 16), "l"(bg + 8));
        asm volatile("cp.async.commit_group;\n");
    };

    const int nt = ksz >> 5;
    load_stage(0, k0);
    load_stage(1, k0 + 32);
    asm volatile("cp.async.wait_group 1;\n");
    __syncthreads();

    for (int tt = 0; tt < nt; tt++) {
        const int buf = tt % 3;
        #pragma unroll
        for (int kp = 0; kp < 2; kp++) {
            unsigned a[4][4], b[4][2];
            #pragma unroll
            for (int mi = 0; mi < 4; mi++) {
                unsigned ad = (unsigned)__cvta_generic_to_shared(
                    &sA[(buf * 128 + wm + mi * 16 + (lane & 15)) * 40 + kp * 16 + ((lane >> 4) << 3)]);
                asm volatile("ldmatrix.sync.aligned.m8n8.x4.shared.b16 {%0,%1,%2,%3}, [%4];\n"
                             : "=r"(a[mi][0]), "=r"(a[mi][1]), "=r"(a[mi][2]), "=r"(a[mi][3])
                             : "r"(ad));
            }
            #pragma unroll
            for (int ni = 0; ni < 4; ni++) {
                unsigned bd = (unsigned)__cvta_generic_to_shared(
                    &sB[(buf * 32 + kp * 16 + (lane & 15)) * 136 + wn + ni * 8]);
                asm volatile("ldmatrix.sync.aligned.m8n8.x2.trans.shared.b16 {%0,%1}, [%2];\n"
                             : "=r"(b[ni][0]), "=r"(b[ni][1]) : "r"(bd));
            }
            #pragma unroll
            for (int mi = 0; mi < 4; mi++)
                #pragma unroll
                for (int ni = 0; ni < 4; ni++)
                    asm volatile(
                        "mma.sync.aligned.m16n8k16.row.col.f32.f16.f16.f32 "
                        "{%0,%1,%2,%3}, {%4,%5,%6,%7}, {%8,%9}, {%0,%1,%2,%3};\n"
                        : "+f"(c[mi][ni][0]), "+f"(c[mi][ni][1]),
                          "+f"(c[mi][ni][2]), "+f"(c[mi][ni][3])
                        : "r"(a[mi][0]), "r"(a[mi][1]), "r"(a[mi][2]), "r"(a[mi][3]),
                          "r"(b[ni][0]), "r"(b[ni][1]));
        }
        if (tt + 2 < nt) {
            load_stage((tt + 2) % 3, k0 + ((tt + 2) << 5));
            asm volatile("cp.async.wait_group 1;\n");
        } else {
            asm volatile("cp.async.wait_group 0;\n");
        }
        __syncthreads();
    }

    const int g = lane >> 2;
    const int t = lane & 3;
    float* Cp = Cpart + (size_t)blockIdx.z * M * Nc;
    #pragma unroll
    for (int mi = 0; mi < 4; mi++) {
        #pragma unroll
        for (int half = 0; half < 2; half++) {
            const int gm = row0 + wm + mi * 16 + g + half * 8;
            if (gm >= M) continue;
            float* Crow = Cp + (size_t)gm * Nc;
            #pragma unroll
            for (int ni = 0; ni < 4; ni++) {
                const int gn = col0 + wn + ni * 8 + 2 * t;
                float2 v;
                v.x = c[mi][ni][half * 2];
                v.y = c[mi][ni][half * 2 + 1];
                *(float2*)&Crow[gn] = v;
            }
        }
    }
}

// plain split-K reduce (+bias, scale) — classifier path
__global__ void reduce4(const float* __restrict__ part, float* __restrict__ out,
                        const float* __restrict__ bias, float scale, int M, int Nc) {
    int i = blockIdx.x * blockDim.x + threadIdx.x;
    if (i >= M * Nc) return;
    size_t st = (size_t)M * Nc;
    float v = part[i] + part[i + st] + part[i + 2 * st] + part[i + 3 * st];
    v *= scale;
    if (bias) v += bias[i % Nc];
    out[i] = v;
}

// layer-1 split-K reduce fused with BN stats (streaming; 440 blocks)
__global__ void reduce4_bn(const float* __restrict__ part, float* __restrict__ out,
                           const float* __restrict__ bias, float scale, int statoff) {
    int t = threadIdx.x;
    int nper = (NN + gridDim.x - 1) / gridDim.x;
    int r0 = blockIdx.x * nper;
    int r1 = min(NN, r0 + nper);
    const size_t st = (size_t)NN * HID;
    float b = bias[t];
    float s = 0.f, s2 = 0.f;
    for (int r = r0; r < r1; r++) {
        size_t i = (size_t)r * HID + t;
        float v = part[i] + part[i + st] + part[i + 2 * st] + part[i + 3 * st];
        v = v * scale + b;
        out[i] = v;
        s += v;
        s2 += v * v;
    }
    atomicAdd(&d_bnstat[statoff + t], s);
    atomicAdd(&d_bnstat[statoff + t + HID], s2);
}

// split-K reduce for h0 fused with layer-0 attention scores
__global__ void reduce4_scores(const float* __restrict__ part, float* __restrict__ out,
                               const float* __restrict__ as0, const float* __restrict__ ad0) {
    int row = blockIdx.x;
    int t = threadIdx.x;
    int i = row * HID + t;
    const size_t st = (size_t)NN * HID;
    float v = part[i] + part[i + st] + part[i + 2 * st] + part[i + 3 * st];
    out[i] = v;
    int head = t >> 5, lane = t & 31;
    float ss = v * as0[t];
    float sd = v * ad0[t];
    #pragma unroll
    for (int o = 16; o > 0; o >>= 1) {
        ss += __shfl_xor_sync(0xffffffffu, ss, o);
        sd += __shfl_xor_sync(0xffffffffu, sd, o);
    }
    if (lane == 0) {
        d_ss[row * NHEAD + head] = ss;
        d_sd[row * NHEAD + head] = sd;
    }
}

// ---------------- host launcher ----------------
extern "C" void kernel_launch(void* const* d_in, const int* in_sizes, int n_in,
                              void* d_out, int out_size) {
    (void)in_sizes; (void)n_in; (void)out_size;
    const float* x   = (const float*)d_in[0];
    const int*   ei  = (const int*)d_in[1];
    const float* W0  = (const float*)d_in[2];
    const float* as0 = (const float*)d_in[3];
    const float* ad0 = (const float*)d_in[4];
    const float* b0  = (const float*)d_in[5];
    const float* g0  = (const float*)d_in[6];
    const float* be0 = (const float*)d_in[7];
    const float* W1  = (const float*)d_in[8];
    const float* as1 = (const float*)d_in[9];
    const float* ad1 = (const float*)d_in[10];
    const float* b1  = (const float*)d_in[11];
    const float* g1  = (const float*)d_in[12];
    const float* be1 = (const float*)d_in[13];
    const float* Wc  = (const float*)d_in[14];
    const float* bc  = (const float*)d_in[15];
    float* out = (float*)d_out;
    const int* srcp = ei;
    const int* dstp = ei + EIN;

    static int smem_set = 0;
    if (!smem_set) {
        cudaFuncSetAttribute(gemm_f16, cudaFuncAttributeMaxDynamicSharedMemorySize, GF16_SMEM);
        smem_set = 1;
    }

    void *p_counts;
    void *p_h0, *p_hin, *p_xh, *p_w0h, *p_aggh, *p_w1h, *p_part, *p_h2, *p_out0, *p_out1;
    cudaGetSymbolAddress(&p_counts, d_counts);
    cudaGetSymbolAddress(&p_h0,   d_h0);
    cudaGetSymbolAddress(&p_hin,  d_hin);
    cudaGetSymbolAddress(&p_xh,   d_xh);
    cudaGetSymbolAddress(&p_w0h,  d_w0h);
    cudaGetSymbolAddress(&p_aggh, d_aggh);
    cudaGetSymbolAddress(&p_w1h,  d_w1h);
    cudaGetSymbolAddress(&p_part, d_part);
    cudaGetSymbolAddress(&p_h2,   d_h2);
    cudaGetSymbolAddress(&p_out0, d_out0);
    cudaGetSymbolAddress(&p_out1, d_out1);
    float*  h0   = (float*)p_h0;
    float*  hin  = (float*)p_hin;
    __half* xh   = (__half*)p_xh;
    __half* w0h  = (__half*)p_w0h;
    __half* aggh = (__half*)p_aggh;
    __half* w1h  = (__half*)p_w1h;
    float*  part = (float*)p_part;
    float*  h2   = (float*)p_h2;
    float*  out0 = (float*)p_out0;
    float*  out1 = (float*)p_out1;

    // ---- CSR build + precomputes (count also zeroes cursor/bnstat) ----
    cudaMemsetAsync(p_counts, 0, (NN + 1) * sizeof(int));
    count_kernel<<<(ETOT + 255) / 256, 256>>>(dstp);
    scan_kernel<<<1, 1024>>>();
    place_kernel<<<(ETOT + 255) / 256, 256>>>(srcp, dstp);
    prep_kernel<<<(PREP_N1 + PREP_N2 + PREP_N3 + 255) / 256, 256>>>(x, W0, W1, as1, ad1);

    // ---- layer 0 ----
    gemm_f16<<<dim3(HID / 128, (NN + 127) / 128, 4), 256, GF16_SMEM>>>(xh, w0h, part, NN, HID,
                                                                       HID, HID / 4);
    reduce4_scores<<<NN, HID>>>(part, h0, as0, ad0);
    softagg0<<<NN, HID>>>(h0, b0, out0);
    bn_partial<<<128, HID>>>(out0, 0);
    bn_apply_scores<<<NN, HID>>>(out0, g0, be0, hin, 0);

    // ---- layer 1 ----
    softagg8<<<NN, HID>>>(hin);
    gemm_f16<<<dim3(HID / 128, (NN + 127) / 128, 4), 256, GF16_SMEM>>>(aggh, w1h, part, NN, HID,
                                                                       KBIG, KBIG / 4);
    reduce4_bn<<<440, HID>>>(part, out1, b1, 1.f / NHEAD, 2 * HID);
    bn_apply<<<(NN * HID + 255) / 256, 256>>>(out1, g1, be1, hin, h2, 2 * HID);

    // ---- classifier (exact f32x2) ----
    gemm128s<<<dim3(1, (NN + 127) / 128, 4), 256>>>(h2, Wc, part, NN, 40, HID, HID / 4);
    reduce4<<<(NN * 40 + 255) / 256, 256>>>(part, out, bc, 1.f, NN, 40);
}

// round 14
// speedup vs baseline: 1.0775x; 1.0775x over previous
#include <cuda_runtime.h>
#include <cuda_fp16.h>
#include <math.h>

#define NN    10000
#define EIN   160000
#define ETOT  170000
#define NHEAD 8
#define HID   256
#define KBIG  (NHEAD * HID)   // 2048
#define EPSI  1e-5f
#define SLOPE 0.2f

typedef unsigned long long ull;

// ---------------- scratch ----------------
__device__ float  d_h0[NN * HID];
__device__ float  d_hin[NN * HID];
__device__ __half d_xh[NN * HID];
__device__ __half d_w0h[HID * HID];
__device__ __half d_aggh[NN * KBIG];
__device__ __half d_w1h[KBIG * HID];
__device__ float  d_part[4 * NN * HID];
__device__ float  d_out0[NN * HID];
__device__ float  d_out1[NN * HID];
__device__ float  d_h2[NN * HID];
__device__ float  d_ss[NN * NHEAD];
__device__ float  d_sd[NN * NHEAD];
__device__ float  d_wsrc[NHEAD * HID];
__device__ float  d_wdst[NHEAD * HID];
__device__ int    d_counts[NN + 1];
__device__ int    d_offsets[NN + 1];
__device__ int    d_cursor[NN];
__device__ int    d_srcs[ETOT];
__device__ float  d_alpha[ETOT * NHEAD];
__device__ float  d_bnstat[4 * HID];

// ---------------- CSR build (count also zeroes cursor + bnstat) ----------------
__global__ void count_kernel(const int* __restrict__ dst) {
    int i = blockIdx.x * blockDim.x + threadIdx.x;
    if (i < NN) d_cursor[i] = 0;
    if (i < 4 * HID) d_bnstat[i] = 0.f;
    if (i >= ETOT) return;
    int d = (i < EIN) ? dst[i] : (i - EIN);
    atomicAdd(&d_counts[d], 1);
}

__global__ void scan_kernel() {
    __shared__ int sums[1024];
    const int n = NN;
    const int chunk = (n + 1023) / 1024;
    int tid = threadIdx.x;
    int start = tid * chunk;
    int local = 0;
    for (int i = 0; i < chunk; i++)
        if (start + i < n) local += d_counts[start + i];
    sums[tid] = local;
    __syncthreads();
    for (int off = 1; off < 1024; off <<= 1) {
        int v = (tid >= off) ? sums[tid - off] : 0;
        __syncthreads();
        sums[tid] += v;
        __syncthreads();
    }
    int run = (tid == 0) ? 0 : sums[tid - 1];
    for (int i = 0; i < chunk; i++) {
        if (start + i < n) {
            d_offsets[start + i] = run;
            run += d_counts[start + i];
        }
    }
    if (tid == 1023) d_offsets[n] = sums[1023];
}

__global__ void place_kernel(const int* __restrict__ src, const int* __restrict__ dst) {
    int i = blockIdx.x * blockDim.x + threadIdx.x;
    if (i >= ETOT) return;
    int s, d;
    if (i < EIN) { s = src[i]; d = dst[i]; }
    else         { s = d = i - EIN; }
    int pos = d_offsets[d] + atomicAdd(&d_cursor[d], 1);
    d_srcs[pos] = s;
}

// ---------------- prep: conv x/W0 to half + W1 permute-to-half + wtilde ----------------
#define PREP_N1 ((NN * HID + HID * HID) / 4)
#define PREP_N2 (KBIG * (HID / 2))
#define PREP_N3 (NHEAD * HID * 32)
__global__ void prep_kernel(const float* __restrict__ x, const float* __restrict__ W0,
                            const float* __restrict__ W1,
                            const float* __restrict__ as1, const float* __restrict__ ad1) {
    int i = blockIdx.x * blockDim.x + threadIdx.x;
    const int nx = NN * HID / 4;
    if (i < PREP_N1) {
        if (i < nx) {
            const float4 v = ((const float4*)x)[i];
            ((__half2*)d_xh)[i * 2]     = __floats2half2_rn(v.x, v.y);
            ((__half2*)d_xh)[i * 2 + 1] = __floats2half2_rn(v.z, v.w);
        } else {
            int j = i - nx;
            const float4 v = ((const float4*)W0)[j];
            ((__half2*)d_w0h)[j * 2]     = __floats2half2_rn(v.x, v.y);
            ((__half2*)d_w0h)[j * 2 + 1] = __floats2half2_rn(v.z, v.w);
        }
    } else if (i < PREP_N1 + PREP_N2) {
        int j = i - PREP_N1;
        int r = j >> 7;
        int c2 = (j & 127) * 2;
        const float* src = W1 + (size_t)(r & 255) * KBIG + (r >> 8) * HID + c2;
        *(__half2*)&d_w1h[(size_t)r * HID + c2] = __floats2half2_rn(src[0], src[1]);
    } else if (i < PREP_N1 + PREP_N2 + PREP_N3) {
        int j = i - PREP_N1 - PREP_N2;
        int w = j >> 5;
        int lane = j & 31;
        int h = w >> 8;
        int k = w & 255;
        const float* wrow = W1 + (size_t)k * KBIG + h * HID;
        const float* ar = as1 + h * HID;
        const float* dr = ad1 + h * HID;
        float s = 0.f, d = 0.f;
        for (int c = lane; c < HID; c += 32) {
            float wv = wrow[c];
            s = fmaf(wv, ar[c], s);
            d = fmaf(wv, dr[c], d);
        }
        #pragma unroll
        for (int o = 16; o > 0; o >>= 1) {
            s += __shfl_xor_sync(0xffffffffu, s, o);
            d += __shfl_xor_sync(0xffffffffu, d, o);
        }
        if (lane == 0) {
            d_wsrc[w] = s;
            d_wdst[w] = d;
        }
    }
}

// ---------------- per-dst edge softmax (4 warps/block, warp per node) ----------------
__global__ void edge_softmax() {
    int w = (blockIdx.x * blockDim.x + threadIdx.x) >> 5;
    if (w >= NN) return;
    int lane = threadIdx.x & 31;
    int beg = d_offsets[w], end = d_offsets[w + 1];
    const float4* ss4 = (const float4*)d_ss;
    float4* al4 = (float4*)d_alpha;

    float sd[NHEAD];
    #pragma unroll
    for (int h = 0; h < NHEAD; h++) sd[h] = d_sd[w * NHEAD + h];

    float mx[NHEAD];
    #pragma unroll
    for (int h = 0; h < NHEAD; h++) mx[h] = -1e30f;
    for (int p = beg + lane; p < end; p += 32) {
        int s = d_srcs[p];
        float4 v0 = ss4[s * 2], v1 = ss4[s * 2 + 1];
        float sv[NHEAD] = {v0.x, v0.y, v0.z, v0.w, v1.x, v1.y, v1.z, v1.w};
        #pragma unroll
        for (int h = 0; h < NHEAD; h++) {
            float sc = sv[h] + sd[h];
            sc = (sc >= 0.f) ? sc : SLOPE * sc;
            mx[h] = fmaxf(mx[h], sc);
        }
    }
    #pragma unroll
    for (int h = 0; h < NHEAD; h++)
        #pragma unroll
        for (int o = 16; o > 0; o >>= 1)
            mx[h] = fmaxf(mx[h], __shfl_xor_sync(0xffffffffu, mx[h], o));

    float sum[NHEAD];
    #pragma unroll
    for (int h = 0; h < NHEAD; h++) sum[h] = 0.f;
    for (int p = beg + lane; p < end; p += 32) {
        int s = d_srcs[p];
        float4 v0 = ss4[s * 2], v1 = ss4[s * 2 + 1];
        float sv[NHEAD] = {v0.x, v0.y, v0.z, v0.w, v1.x, v1.y, v1.z, v1.w};
        float ev[NHEAD];
        #pragma unroll
        for (int h = 0; h < NHEAD; h++) {
            float sc = sv[h] + sd[h];
            sc = (sc >= 0.f) ? sc : SLOPE * sc;
            float e = __expf(sc - mx[h]);
            sum[h] += e;
            ev[h] = e;
        }
        al4[p * 2]     = make_float4(ev[0], ev[1], ev[2], ev[3]);
        al4[p * 2 + 1] = make_float4(ev[4], ev[5], ev[6], ev[7]);
    }
    #pragma unroll
    for (int h = 0; h < NHEAD; h++)
        #pragma unroll
        for (int o = 16; o > 0; o >>= 1)
            sum[h] += __shfl_xor_sync(0xffffffffu, sum[h], o);

    float r0 = 1.f / sum[0], r1 = 1.f / sum[1], r2 = 1.f / sum[2], r3 = 1.f / sum[3];
    float r4 = 1.f / sum[4], r5 = 1.f / sum[5], r6 = 1.f / sum[6], r7 = 1.f / sum[7];

    for (int p = beg + lane; p < end; p += 32) {
        float4 e0 = al4[p * 2], e1 = al4[p * 2 + 1];
        e0.x *= r0; e0.y *= r1; e0.z *= r2; e0.w *= r3;
        e1.x *= r4; e1.y *= r5; e1.z *= r6; e1.w *= r7;
        al4[p * 2]     = e0;
        al4[p * 2 + 1] = e1;
    }
}

// ---------------- aggregation (block per node) ----------------
__global__ void aggregate_c32(const float* __restrict__ h,
                              const float* __restrict__ bias,
                              float* __restrict__ out) {
    int nod = blockIdx.x;
    int t = threadIdx.x;
    int head = t >> 5;
    int beg = d_offsets[nod], end = d_offsets[nod + 1];
    float acc = 0.f;
    int p = beg;
    for (; p + 2 <= end; p += 2) {
        int s0 = d_srcs[p], s1 = d_srcs[p + 1];
        float a0 = d_alpha[p * NHEAD + head];
        float a1 = d_alpha[(p + 1) * NHEAD + head];
        float v0 = h[(size_t)s0 * HID + t];
        float v1 = h[(size_t)s1 * HID + t];
        acc = fmaf(v0, a0, acc);
        acc = fmaf(v1, a1, acc);
    }
    if (p < end) {
        float a = d_alpha[p * NHEAD + head];
        acc = fmaf(h[(size_t)d_srcs[p] * HID + t], a, acc);
    }
    out[(size_t)nod * HID + t] = acc + bias[t];
}

__global__ void aggregate8(const float* __restrict__ hin) {
    int nod = blockIdx.x;
    int t = threadIdx.x;
    int beg = d_offsets[nod], end = d_offsets[nod + 1];
    const float4* al4 = (const float4*)d_alpha;
    float acc[NHEAD];
    #pragma unroll
    for (int i = 0; i < NHEAD; i++) acc[i] = 0.f;
    int p = beg;
    for (; p + 4 <= end; p += 4) {
        int sidx[4];
        #pragma unroll
        for (int e = 0; e < 4; e++) sidx[e] = d_srcs[p + e];
        float v[4];
        #pragma unroll
        for (int e = 0; e < 4; e++) v[e] = hin[(size_t)sidx[e] * HID + t];
        #pragma unroll
        for (int e = 0; e < 4; e++) {
            float4 a0 = al4[(p + e) * 2], a1 = al4[(p + e) * 2 + 1];
            float al[NHEAD] = {a0.x, a0.y, a0.z, a0.w, a1.x, a1.y, a1.z, a1.w};
            #pragma unroll
            for (int i = 0; i < NHEAD; i++) acc[i] = fmaf(v[e], al[i], acc[i]);
        }
    }
    for (; p < end; p++) {
        int s = d_srcs[p];
        float v = hin[(size_t)s * HID + t];
        float4 a0 = al4[p * 2], a1 = al4[p * 2 + 1];
        float al[NHEAD] = {a0.x, a0.y, a0.z, a0.w, a1.x, a1.y, a1.z, a1.w};
        #pragma unroll
        for (int i = 0; i < NHEAD; i++) acc[i] = fmaf(v, al[i], acc[i]);
    }
    __half* op = d_aggh + (size_t)nod * KBIG + t;
    #pragma unroll
    for (int i = 0; i < NHEAD; i++) op[i * HID] = __float2half_rn(acc[i]);
}

// ---------------- batch norm ----------------
__device__ __forceinline__ void bn_coeff(int statoff, int c, float& mu, float& rinv) {
    float m = d_bnstat[statoff + c] * (1.f / NN);
    float v = d_bnstat[statoff + c + HID] * (1.f / NN) - m * m;
    mu = m;
    rinv = rsqrtf(v + EPSI);
}

__global__ void bn_partial(const float* __restrict__ x, int statoff) {
    int c = threadIdx.x;
    int nb = gridDim.x;
    int rows = (NN + nb - 1) / nb;
    int r0 = blockIdx.x * rows;
    int r1 = min(NN, r0 + rows);
    float s = 0.f, s2 = 0.f;
    for (int r = r0; r < r1; r++) {
        float v = x[(size_t)r * HID + c];
        s += v; s2 += v * v;
    }
    atomicAdd(&d_bnstat[statoff + c], s);
    atomicAdd(&d_bnstat[statoff + c + HID], s2);
}

__global__ void bn_apply(const float* __restrict__ x,
                         const float* __restrict__ g,
                         const float* __restrict__ be,
                         const float* __restrict__ resid,
                         float* __restrict__ out, int statoff) {
    int i = blockIdx.x * blockDim.x + threadIdx.x;
    if (i >= NN * HID) return;
    int c = i & (HID - 1);
    float mu, rinv;
    bn_coeff(statoff, c, mu, rinv);
    float v = g[c] * (x[i] - mu) * rinv + be[c];
    v = (v > 0.f) ? v : (expf(v) - 1.f);
    if (resid) v += resid[i];
    out[i] = v;
}

__global__ void bn_apply_scores(const float* __restrict__ x,
                                const float* __restrict__ g,
                                const float* __restrict__ be,
                                float* __restrict__ out, int statoff) {
    __shared__ float srow[HID];
    int row = blockIdx.x;
    int t = threadIdx.x;
    int i = row * HID + t;
    float mu, rinv;
    bn_coeff(statoff, t, mu, rinv);
    float v = g[t] * (x[i] - mu) * rinv + be[t];
    v = (v > 0.f) ? v : (expf(v) - 1.f);
    out[i] = v;
    srow[t] = v;
    __syncthreads();
    int head = t >> 5, lane = t & 31;
    float as = 0.f, ad = 0.f;
    #pragma unroll
    for (int cc = 0; cc < HID / 32; cc++) {
        int c2 = cc * 32 + lane;
        float vv = srow[c2];
        as = fmaf(vv, d_wsrc[head * HID + c2], as);
        ad = fmaf(vv, d_wdst[head * HID + c2], ad);
    }
    #pragma unroll
    for (int o = 16; o > 0; o >>= 1) {
        as += __shfl_xor_sync(0xffffffffu, as, o);
        ad += __shfl_xor_sync(0xffffffffu, ad, o);
    }
    if (lane == 0) {
        d_ss[row * NHEAD + head] = as;
        d_sd[row * NHEAD + head] = ad;
    }
}

// ---------------- fp32 split-K GEMM (f32x2, exact; classifier only) ----------------
__global__ __launch_bounds__(256, 2) void gemm128s(const float* __restrict__ A,
                                                   const float* __restrict__ B,
                                                   float* __restrict__ Cpart,
                                                   int M, int Nc, int lda, int ksz) {
    __shared__ float As[2][8][132];
    __shared__ float Bs[2][8][132];

    const int tid  = threadIdx.x;
    const int row0 = blockIdx.y * 128;
    const int col0 = blockIdx.x * 128;
    const int k0   = blockIdx.z * ksz;

    const int arow = tid >> 1;
    const int akg  = (tid & 1) * 4;
    const int bkr  = tid >> 5;
    const int bc4  = (tid & 31) * 4;

    const int lane = tid & 31;
    const int warp = tid >> 5;
    const int m0 = (warp & 3) * 32 + (lane >> 3) * 4;
    const int n0 = (warp >> 2) * 64 + (lane & 7) * 4;

    const int gra = row0 + arow;
    const int gcb = col0 + bc4;

    ull acc[8][4];
    #pragma unroll
    for (int i = 0; i < 8; i++)
        #pragma unroll
        for (int j = 0; j < 4; j++) acc[i][j] = 0ull;

    float aL[4], bL[4];

    auto load_tile = [&](int kabs) {
        if (gra < M) {
            const float4 v = *(const float4*)&A[(size_t)gra * lda + kabs + akg];
            aL[0] = v.x; aL[1] = v.y; aL[2] = v.z; aL[3] = v.w;
        } else {
            aL[0] = aL[1] = aL[2] = aL[3] = 0.f;
        }
        const float* Brow = B + (size_t)(kabs + bkr) * Nc;
        if (gcb + 4 <= Nc) {
            const float4 v = *(const float4*)&Brow[gcb];
            bL[0] = v.x; bL[1] = v.y; bL[2] = v.z; bL[3] = v.w;
        } else {
            #pragma unroll
            for (int i = 0; i < 4; i++)
                bL[i] = (gcb + i < Nc) ? Brow[gcb + i] : 0.f;
        }
    };
    auto store_tile = [&](int buf) {
        #pragma unroll
        for (int i = 0; i < 4; i++) As[buf][akg + i][arow] = aL[i];
        *(float4*)&Bs[buf][bkr][bc4] = make_float4(bL[0], bL[1], bL[2], bL[3]);
    };

    load_tile(k0);
    store_tile(0);
    __syncthreads();

    const int ntiles = ksz >> 3;
    for (int t = 0; t < ntiles; t++) {
        const int buf = t & 1;
        if (t + 1 < ntiles) load_tile(k0 + ((t + 1) << 3));
        #pragma unroll
        for (int k = 0; k < 8; k++) {
            float a_f[8];
            *(float4*)&a_f[0] = *(const float4*)&As[buf][k][m0];
            *(float4*)&a_f[4] = *(const float4*)&As[buf][k][m0 + 16];
            float4 bv0 = *(const float4*)&Bs[buf][k][n0];
            float4 bv1 = *(const float4*)&Bs[buf][k][n0 + 32];
            ull b2[4];
            asm("mov.b64 %0, {%1, %2};" : "=l"(b2[0]) : "f"(bv0.x), "f"(bv0.y));
            asm("mov.b64 %0, {%1, %2};" : "=l"(b2[1]) : "f"(bv0.z), "f"(bv0.w));
            asm("mov.b64 %0, {%1, %2};" : "=l"(b2[2]) : "f"(bv1.x), "f"(bv1.y));
            asm("mov.b64 %0, {%1, %2};" : "=l"(b2[3]) : "f"(bv1.z), "f"(bv1.w));
            #pragma unroll
            for (int i = 0; i < 8; i++) {
                ull a2;
                asm("mov.b64 %0, {%1, %1};" : "=l"(a2) : "f"(a_f[i]));
                #pragma unroll
                for (int j = 0; j < 4; j++)
                    asm("fma.rn.f32x2 %0, %1, %2, %0;"
                        : "+l"(acc[i][j]) : "l"(a2), "l"(b2[j]));
            }
        }
        if (t + 1 < ntiles) {
            store_tile(buf ^ 1);
            __syncthreads();
        }
    }

    float* Cp = Cpart + (size_t)blockIdx.z * M * Nc;
    #pragma unroll
    for (int i = 0; i < 8; i++) {
        const int gm = row0 + ((i < 4) ? (m0 + i) : (m0 + 16 + i - 4));
        if (gm >= M) continue;
        float* Crow = Cp + (size_t)gm * Nc;
        #pragma unroll
        for (int jj = 0; jj < 2; jj++) {
            const int gn = col0 + n0 + jj * 32;
            float v[4];
            asm("mov.b64 {%0, %1}, %2;" : "=f"(v[0]), "=f"(v[1]) : "l"(acc[i][jj * 2]));
            asm("mov.b64 {%0, %1}, %2;" : "=f"(v[2]), "=f"(v[3]) : "l"(acc[i][jj * 2 + 1]));
            if (gn + 4 <= Nc) {
                *(float4*)&Crow[gn] = make_float4(v[0], v[1], v[2], v[3]);
            } else {
                #pragma unroll
                for (int j = 0; j < 4; j++)
                    if (gn + j < Nc) Crow[gn + j] = v[j];
            }
        }
    }
}

// ---------------- fp16 tensor-core GEMM: 3-stage cp.async + ldmatrix + m16n8k16 ----------------
#define GF16_A_STRIDE (128 * 40)
#define GF16_B_STRIDE (32 * 136)
#define GF16_SMEM ((3 * (GF16_A_STRIDE + GF16_B_STRIDE)) * (int)sizeof(__half))

__global__ __launch_bounds__(256, 2) void gemm_f16(const __half* __restrict__ A,
                                                   const __half* __restrict__ B,
                                                   float* __restrict__ Cpart,
                                                   int M, int Nc, int lda, int ksz) {
    extern __shared__ __half sm16[];
    __half* sA = sm16;
    __half* sB = sm16 + 3 * GF16_A_STRIDE;

    const int tid  = threadIdx.x;
    const int row0 = blockIdx.y * 128;
    const int col0 = blockIdx.x * 128;
    const int k0   = blockIdx.z * ksz;
    const int lane = tid & 31;
    const int warp = tid >> 5;
    const int wm   = (warp >> 2) * 64;
    const int wn   = (warp & 3) * 32;

    const int ar = tid >> 1;
    const int ac = (tid & 1) * 16;
    const int br = tid >> 3;
    const int bc = (tid & 7) * 16;

    float c[4][4][4];
    #pragma unroll
    for (int mi = 0; mi < 4; mi++)
        #pragma unroll
        for (int ni = 0; ni < 4; ni++)
            #pragma unroll
            for (int q = 0; q < 4; q++) c[mi][ni][q] = 0.f;

    auto load_stage = [&](int st, int kabs) {
        const __half* ag = A + (size_t)(row0 + ar) * lda + kabs + ac;
        int pa = (row0 + ar < M) ? 16 : 0;
        unsigned sa = (unsigned)__cvta_generic_to_shared(&sA[(st * 128 + ar) * 40 + ac]);
        asm volatile("cp.async.cg.shared.global [%0], [%1], 16, %2;\n" :: "r"(sa), "l"(ag), "r"(pa));
        asm volatile("cp.async.cg.shared.global [%0], [%1], 16, %2;\n" :: "r"(sa + 16), "l"(ag + 8), "r"(pa));
        const __half* bg = B + (size_t)(kabs + br) * Nc + col0 + bc;
        unsigned sb = (unsigned)__cvta_generic_to_shared(&sB[(st * 32 + br) * 136 + bc]);
        asm volatile("cp.async.cg.shared.global [%0], [%1], 16;\n" :: "r"(sb), "l"(bg));
        asm volatile("cp.async.cg.shared.global [%0], [%1], 16;\n" :: "r"(sb + 16), "l"(bg + 8));
        asm volatile("cp.async.commit_group;\n");
    };

    const int nt = ksz >> 5;
    load_stage(0, k0);
    load_stage(1, k0 + 32);
    asm volatile("cp.async.wait_group 1;\n");
    __syncthreads();

    for (int tt = 0; tt < nt; tt++) {
        const int buf = tt % 3;
        #pragma unroll
        for (int kp = 0; kp < 2; kp++) {
            unsigned a[4][4], b[4][2];
            #pragma unroll
            for (int mi = 0; mi < 4; mi++) {
                unsigned ad = (unsigned)__cvta_generic_to_shared(
                    &sA[(buf * 128 + wm + mi * 16 + (lane & 15)) * 40 + kp * 16 + ((lane >> 4) << 3)]);
                asm volatile("ldmatrix.sync.aligned.m8n8.x4.shared.b16 {%0,%1,%2,%3}, [%4];\n"
                             : "=r"(a[mi][0]), "=r"(a[mi][1]), "=r"(a[mi][2]), "=r"(a[mi][3])
                             : "r"(ad));
            }
            #pragma unroll
            for (int ni = 0; ni < 4; ni++) {
                unsigned bd = (unsigned)__cvta_generic_to_shared(
                    &sB[(buf * 32 + kp * 16 + (lane & 15)) * 136 + wn + ni * 8]);
                asm volatile("ldmatrix.sync.aligned.m8n8.x2.trans.shared.b16 {%0,%1}, [%2];\n"
                             : "=r"(b[ni][0]), "=r"(b[ni][1]) : "r"(bd));
            }
            #pragma unroll
            for (int mi = 0; mi < 4; mi++)
                #pragma unroll
                for (int ni = 0; ni < 4; ni++)
                    asm volatile(
                        "mma.sync.aligned.m16n8k16.row.col.f32.f16.f16.f32 "
                        "{%0,%1,%2,%3}, {%4,%5,%6,%7}, {%8,%9}, {%0,%1,%2,%3};\n"
                        : "+f"(c[mi][ni][0]), "+f"(c[mi][ni][1]),
                          "+f"(c[mi][ni][2]), "+f"(c[mi][ni][3])
                        : "r"(a[mi][0]), "r"(a[mi][1]), "r"(a[mi][2]), "r"(a[mi][3]),
                          "r"(b[ni][0]), "r"(b[ni][1]));
        }
        if (tt + 2 < nt) {
            load_stage((tt + 2) % 3, k0 + ((tt + 2) << 5));
            asm volatile("cp.async.wait_group 1;\n");
        } else {
            asm volatile("cp.async.wait_group 0;\n");
        }
        __syncthreads();
    }

    const int g = lane >> 2;
    const int t = lane & 3;
    float* Cp = Cpart + (size_t)blockIdx.z * M * Nc;
    #pragma unroll
    for (int mi = 0; mi < 4; mi++) {
        #pragma unroll
        for (int half = 0; half < 2; half++) {
            const int gm = row0 + wm + mi * 16 + g + half * 8;
            if (gm >= M) continue;
            float* Crow = Cp + (size_t)gm * Nc;
            #pragma unroll
            for (int ni = 0; ni < 4; ni++) {
                const int gn = col0 + wn + ni * 8 + 2 * t;
                float2 v;
                v.x = c[mi][ni][half * 2];
                v.y = c[mi][ni][half * 2 + 1];
                *(float2*)&Crow[gn] = v;
            }
        }
    }
}

// classifier split-4 reduce (+bias)
__global__ void reduce4(const float* __restrict__ part, float* __restrict__ out,
                        const float* __restrict__ bias, float scale, int M, int Nc) {
    int i = blockIdx.x * blockDim.x + threadIdx.x;
    if (i >= M * Nc) return;
    size_t st = (size_t)M * Nc;
    float v = part[i] + part[i + st] + part[i + 2 * st] + part[i + 3 * st];
    v *= scale;
    if (bias) v += bias[i % Nc];
    out[i] = v;
}

// layer-1 split-2 reduce fused with BN stats (streaming; 440 blocks)
__global__ void reduce2_bn(const float* __restrict__ part, float* __restrict__ out,
                           const float* __restrict__ bias, float scale, int statoff) {
    int t = threadIdx.x;
    int nper = (NN + gridDim.x - 1) / gridDim.x;
    int r0 = blockIdx.x * nper;
    int r1 = min(NN, r0 + nper);
    const size_t st = (size_t)NN * HID;
    float b = bias[t];
    float s = 0.f, s2 = 0.f;
    for (int r = r0; r < r1; r++) {
        size_t i = (size_t)r * HID + t;
        float v = part[i] + part[i + st];
        v = v * scale + b;
        out[i] = v;
        s += v;
        s2 += v * v;
    }
    atomicAdd(&d_bnstat[statoff + t], s);
    atomicAdd(&d_bnstat[statoff + t + HID], s2);
}

// layer-0 split-2 reduce fused with attention scores (block = row)
__global__ void reduce2_scores(const float* __restrict__ part, float* __restrict__ out,
                               const float* __restrict__ as0, const float* __restrict__ ad0) {
    int row = blockIdx.x;
    int t = threadIdx.x;
    int i = row * HID + t;
    const size_t st = (size_t)NN * HID;
    float v = part[i] + part[i + st];
    out[i] = v;
    int head = t >> 5, lane = t & 31;
    float ss = v * as0[t];
    float sd = v * ad0[t];
    #pragma unroll
    for (int o = 16; o > 0; o >>= 1) {
        ss += __shfl_xor_sync(0xffffffffu, ss, o);
        sd += __shfl_xor_sync(0xffffffffu, sd, o);
    }
    if (lane == 0) {
        d_ss[row * NHEAD + head] = ss;
        d_sd[row * NHEAD + head] = sd;
    }
}

// ---------------- host launcher ----------------
extern "C" void kernel_launch(void* const* d_in, const int* in_sizes, int n_in,
                              void* d_out, int out_size) {
    (void)in_sizes; (void)n_in; (void)out_size;
    const float* x   = (const float*)d_in[0];
    const int*   ei  = (const int*)d_in[1];
    const float* W0  = (const float*)d_in[2];
    const float* as0 = (const float*)d_in[3];
    const float* ad0 = (const float*)d_in[4];
    const float* b0  = (const float*)d_in[5];
    const float* g0  = (const float*)d_in[6];
    const float* be0 = (const float*)d_in[7];
    const float* W1  = (const float*)d_in[8];
    const float* as1 = (const float*)d_in[9];
    const float* ad1 = (const float*)d_in[10];
    const float* b1  = (const float*)d_in[11];
    const float* g1  = (const float*)d_in[12];
    const float* be1 = (const float*)d_in[13];
    const float* Wc  = (const float*)d_in[14];
    const float* bc  = (const float*)d_in[15];
    float* out = (float*)d_out;
    const int* srcp = ei;
    const int* dstp = ei + EIN;

    static int smem_set = 0;
    if (!smem_set) {
        cudaFuncSetAttribute(gemm_f16, cudaFuncAttributeMaxDynamicSharedMemorySize, GF16_SMEM);
        smem_set = 1;
    }

    void *p_counts;
    void *p_h0, *p_hin, *p_xh, *p_w0h, *p_aggh, *p_w1h, *p_part, *p_h2, *p_out0, *p_out1;
    cudaGetSymbolAddress(&p_counts, d_counts);
    cudaGetSymbolAddress(&p_h0,   d_h0);
    cudaGetSymbolAddress(&p_hin,  d_hin);
    cudaGetSymbolAddress(&p_xh,   d_xh);
    cudaGetSymbolAddress(&p_w0h,  d_w0h);
    cudaGetSymbolAddress(&p_aggh, d_aggh);
    cudaGetSymbolAddress(&p_w1h,  d_w1h);
    cudaGetSymbolAddress(&p_part, d_part);
    cudaGetSymbolAddress(&p_h2,   d_h2);
    cudaGetSymbolAddress(&p_out0, d_out0);
    cudaGetSymbolAddress(&p_out1, d_out1);
    float*  h0   = (float*)p_h0;
    float*  hin  = (float*)p_hin;
    __half* xh   = (__half*)p_xh;
    __half* w0h  = (__half*)p_w0h;
    __half* aggh = (__half*)p_aggh;
    __half* w1h  = (__half*)p_w1h;
    float*  part = (float*)p_part;
    float*  h2   = (float*)p_h2;
    float*  out0 = (float*)p_out0;
    float*  out1 = (float*)p_out1;

    // ---- CSR build + precomputes ----
    cudaMemsetAsync(p_counts, 0, (NN + 1) * sizeof(int));
    count_kernel<<<(ETOT + 255) / 256, 256>>>(dstp);
    scan_kernel<<<1, 1024>>>();
    place_kernel<<<(ETOT + 255) / 256, 256>>>(srcp, dstp);
    prep_kernel<<<(PREP_N1 + PREP_N2 + PREP_N3 + 255) / 256, 256>>>(x, W0, W1, as1, ad1);

    // ---- layer 0 (split-K=2) ----
    gemm_f16<<<dim3(HID / 128, (NN + 127) / 128, 2), 256, GF16_SMEM>>>(xh, w0h, part, NN, HID,
                                                                       HID, HID / 2);
    reduce2_scores<<<NN, HID>>>(part, h0, as0, ad0);
    edge_softmax<<<(NN + 3) / 4, 128>>>();
    aggregate_c32<<<NN, HID>>>(h0, b0, out0);
    bn_partial<<<128, HID>>>(out0, 0);
    bn_apply_scores<<<NN, HID>>>(out0, g0, be0, hin, 0);

    // ---- layer 1 (split-K=2) ----
    edge_softmax<<<(NN + 3) / 4, 128>>>();
    aggregate8<<<NN, HID>>>(hin);
    gemm_f16<<<dim3(HID / 128, (NN + 127) / 128, 2), 256, GF16_SMEM>>>(aggh, w1h, part, NN, HID,
                                                                       KBIG, KBIG / 2);
    reduce2_bn<<<440, HID>>>(part, out1, b1, 1.f / NHEAD, 2 * HID);
    bn_apply<<<(NN * HID + 255) / 256, 256>>>(out1, g1, be1, hin, h2, 2 * HID);

    // ---- classifier (exact f32x2, split-4) ----
    gemm128s<<<dim3(1, (NN + 127) / 128, 4), 256>>>(h2, Wc, part, NN, 40, HID, HID / 4);
    reduce4<<<(NN * 40 + 255) / 256, 256>>>(part, out, bc, 1.f, NN, 40);
}

// round 15
// speedup vs baseline: 1.2179x; 1.1303x over previous
#include <cuda_runtime.h>
#include <cuda_fp16.h>
#include <math.h>

#define NN    10000
#define EIN   160000
#define ETOT  170000
#define NHEAD 8
#define HID   256
#define KBIG  (NHEAD * HID)   // 2048
#define EPSI  1e-5f
#define SLOPE 0.2f

typedef unsigned long long ull;

// ---------------- scratch ----------------
__device__ float  d_h0[NN * HID];
__device__ float  d_hin[NN * HID];
__device__ __half d_xh[NN * HID];
__device__ __half d_w0h[HID * HID];
__device__ __half d_aggh[NN * KBIG];
__device__ __half d_w1h[KBIG * HID];
__device__ float  d_part[4 * NN * HID];
__device__ float  d_out0[NN * HID];
__device__ float  d_out1[NN * HID];
__device__ float  d_h2[NN * HID];
__device__ float  d_ss[NN * NHEAD];
__device__ float  d_sd[NN * NHEAD];
__device__ float  d_wsrc[NHEAD * HID];
__device__ float  d_wdst[NHEAD * HID];
__device__ int    d_counts[NN + 1];
__device__ int    d_offsets[NN + 1];
__device__ int    d_cursor[NN];
__device__ int    d_srcs[ETOT];
__device__ float  d_alpha[ETOT * NHEAD];
__device__ float  d_bnstat[4 * HID];

// ---------------- CSR build (count also zeroes cursor + bnstat) ----------------
__global__ void count_kernel(const int* __restrict__ dst) {
    int i = blockIdx.x * blockDim.x + threadIdx.x;
    if (i < NN) d_cursor[i] = 0;
    if (i < 4 * HID) d_bnstat[i] = 0.f;
    if (i >= ETOT) return;
    int d = (i < EIN) ? dst[i] : (i - EIN);
    atomicAdd(&d_counts[d], 1);
}

__global__ void scan_kernel() {
    __shared__ int sums[1024];
    const int n = NN;
    const int chunk = (n + 1023) / 1024;
    int tid = threadIdx.x;
    int start = tid * chunk;
    int local = 0;
    for (int i = 0; i < chunk; i++)
        if (start + i < n) local += d_counts[start + i];
    sums[tid] = local;
    __syncthreads();
    for (int off = 1; off < 1024; off <<= 1) {
        int v = (tid >= off) ? sums[tid - off] : 0;
        __syncthreads();
        sums[tid] += v;
        __syncthreads();
    }
    int run = (tid == 0) ? 0 : sums[tid - 1];
    for (int i = 0; i < chunk; i++) {
        if (start + i < n) {
            d_offsets[start + i] = run;
            run += d_counts[start + i];
        }
    }
    if (tid == 1023) d_offsets[n] = sums[1023];
}

__global__ void place_kernel(const int* __restrict__ src, const int* __restrict__ dst) {
    int i = blockIdx.x * blockDim.x + threadIdx.x;
    if (i >= ETOT) return;
    int s, d;
    if (i < EIN) { s = src[i]; d = dst[i]; }
    else         { s = d = i - EIN; }
    int pos = d_offsets[d] + atomicAdd(&d_cursor[d], 1);
    d_srcs[pos] = s;
}

// ---------------- prep: conv x/W0 to half + W1 permute-to-half + wtilde ----------------
#define PREP_N1 ((NN * HID + HID * HID) / 4)
#define PREP_N2 (KBIG * (HID / 2))
#define PREP_N3 (NHEAD * HID * 32)
__global__ void prep_kernel(const float* __restrict__ x, const float* __restrict__ W0,
                            const float* __restrict__ W1,
                            const float* __restrict__ as1, const float* __restrict__ ad1) {
    int i = blockIdx.x * blockDim.x + threadIdx.x;
    const int nx = NN * HID / 4;
    if (i < PREP_N1) {
        if (i < nx) {
            const float4 v = ((const float4*)x)[i];
            ((__half2*)d_xh)[i * 2]     = __floats2half2_rn(v.x, v.y);
            ((__half2*)d_xh)[i * 2 + 1] = __floats2half2_rn(v.z, v.w);
        } else {
            int j = i - nx;
            const float4 v = ((const float4*)W0)[j];
            ((__half2*)d_w0h)[j * 2]     = __floats2half2_rn(v.x, v.y);
            ((__half2*)d_w0h)[j * 2 + 1] = __floats2half2_rn(v.z, v.w);
        }
    } else if (i < PREP_N1 + PREP_N2) {
        int j = i - PREP_N1;
        int r = j >> 7;
        int c2 = (j & 127) * 2;
        const float* src = W1 + (size_t)(r & 255) * KBIG + (r >> 8) * HID + c2;
        *(__half2*)&d_w1h[(size_t)r * HID + c2] = __floats2half2_rn(src[0], src[1]);
    } else if (i < PREP_N1 + PREP_N2 + PREP_N3) {
        int j = i - PREP_N1 - PREP_N2;
        int w = j >> 5;
        int lane = j & 31;
        int h = w >> 8;
        int k = w & 255;
        const float* wrow = W1 + (size_t)k * KBIG + h * HID;
        const float* ar = as1 + h * HID;
        const float* dr = ad1 + h * HID;
        float s = 0.f, d = 0.f;
        for (int c = lane; c < HID; c += 32) {
            float wv = wrow[c];
            s = fmaf(wv, ar[c], s);
            d = fmaf(wv, dr[c], d);
        }
        #pragma unroll
        for (int o = 16; o > 0; o >>= 1) {
            s += __shfl_xor_sync(0xffffffffu, s, o);
            d += __shfl_xor_sync(0xffffffffu, d, o);
        }
        if (lane == 0) {
            d_wsrc[w] = s;
            d_wdst[w] = d;
        }
    }
}

// ---------------- per-dst edge softmax (4 warps/block, warp per node) ----------------
__global__ void edge_softmax() {
    int w = (blockIdx.x * blockDim.x + threadIdx.x) >> 5;
    if (w >= NN) return;
    int lane = threadIdx.x & 31;
    int beg = d_offsets[w], end = d_offsets[w + 1];
    const float4* ss4 = (const float4*)d_ss;
    float4* al4 = (float4*)d_alpha;

    float sd[NHEAD];
    #pragma unroll
    for (int h = 0; h < NHEAD; h++) sd[h] = d_sd[w * NHEAD + h];

    float mx[NHEAD];
    #pragma unroll
    for (int h = 0; h < NHEAD; h++) mx[h] = -1e30f;
    for (int p = beg + lane; p < end; p += 32) {
        int s = d_srcs[p];
        float4 v0 = ss4[s * 2], v1 = ss4[s * 2 + 1];
        float sv[NHEAD] = {v0.x, v0.y, v0.z, v0.w, v1.x, v1.y, v1.z, v1.w};
        #pragma unroll
        for (int h = 0; h < NHEAD; h++) {
            float sc = sv[h] + sd[h];
            sc = (sc >= 0.f) ? sc : SLOPE * sc;
            mx[h] = fmaxf(mx[h], sc);
        }
    }
    #pragma unroll
    for (int h = 0; h < NHEAD; h++)
        #pragma unroll
        for (int o = 16; o > 0; o >>= 1)
            mx[h] = fmaxf(mx[h], __shfl_xor_sync(0xffffffffu, mx[h], o));

    float sum[NHEAD];
    #pragma unroll
    for (int h = 0; h < NHEAD; h++) sum[h] = 0.f;
    for (int p = beg + lane; p < end; p += 32) {
        int s = d_srcs[p];
        float4 v0 = ss4[s * 2], v1 = ss4[s * 2 + 1];
        float sv[NHEAD] = {v0.x, v0.y, v0.z, v0.w, v1.x, v1.y, v1.z, v1.w};
        float ev[NHEAD];
        #pragma unroll
        for (int h = 0; h < NHEAD; h++) {
            float sc = sv[h] + sd[h];
            sc = (sc >= 0.f) ? sc : SLOPE * sc;
            float e = __expf(sc - mx[h]);
            sum[h] += e;
            ev[h] = e;
        }
        al4[p * 2]     = make_float4(ev[0], ev[1], ev[2], ev[3]);
        al4[p * 2 + 1] = make_float4(ev[4], ev[5], ev[6], ev[7]);
    }
    #pragma unroll
    for (int h = 0; h < NHEAD; h++)
        #pragma unroll
        for (int o = 16; o > 0; o >>= 1)
            sum[h] += __shfl_xor_sync(0xffffffffu, sum[h], o);

    float r0 = 1.f / sum[0], r1 = 1.f / sum[1], r2 = 1.f / sum[2], r3 = 1.f / sum[3];
    float r4 = 1.f / sum[4], r5 = 1.f / sum[5], r6 = 1.f / sum[6], r7 = 1.f / sum[7];

    for (int p = beg + lane; p < end; p += 32) {
        float4 e0 = al4[p * 2], e1 = al4[p * 2 + 1];
        e0.x *= r0; e0.y *= r1; e0.z *= r2; e0.w *= r3;
        e1.x *= r4; e1.y *= r5; e1.z *= r6; e1.w *= r7;
        al4[p * 2]     = e0;
        al4[p * 2 + 1] = e1;
    }
}

// ---------------- aggregation: 128 threads, float2 per thread (half LDG issue) ----------------
__global__ void aggregate_c32(const float* __restrict__ h,
                              const float* __restrict__ bias,
                              float* __restrict__ out) {
    int nod = blockIdx.x;
    int t = threadIdx.x;            // 0..127; channels 2t, 2t+1 (same head)
    int head = t >> 4;
    int beg = d_offsets[nod], end = d_offsets[nod + 1];
    float acc0 = 0.f, acc1 = 0.f;
    int p = beg;
    for (; p + 2 <= end; p += 2) {
        int s0 = d_srcs[p], s1 = d_srcs[p + 1];
        float a0 = d_alpha[p * NHEAD + head];
        float a1 = d_alpha[(p + 1) * NHEAD + head];
        float2 v0 = *(const float2*)&h[(size_t)s0 * HID + 2 * t];
        float2 v1 = *(const float2*)&h[(size_t)s1 * HID + 2 * t];
        acc0 = fmaf(v0.x, a0, acc0);
        acc1 = fmaf(v0.y, a0, acc1);
        acc0 = fmaf(v1.x, a1, acc0);
        acc1 = fmaf(v1.y, a1, acc1);
    }
    if (p < end) {
        float a = d_alpha[p * NHEAD + head];
        float2 v = *(const float2*)&h[(size_t)d_srcs[p] * HID + 2 * t];
        acc0 = fmaf(v.x, a, acc0);
        acc1 = fmaf(v.y, a, acc1);
    }
    float2 b = *(const float2*)&bias[2 * t];
    *(float2*)&out[(size_t)nod * HID + 2 * t] = make_float2(acc0 + b.x, acc1 + b.y);
}

__global__ void aggregate8(const float* __restrict__ hin) {
    int nod = blockIdx.x;
    int t = threadIdx.x;            // 0..127; channels 2t, 2t+1
    int beg = d_offsets[nod], end = d_offsets[nod + 1];
    const float4* al4 = (const float4*)d_alpha;
    float2 acc[NHEAD];
    #pragma unroll
    for (int i = 0; i < NHEAD; i++) acc[i] = make_float2(0.f, 0.f);
    int p = beg;
    for (; p + 2 <= end; p += 2) {
        int s0 = d_srcs[p], s1 = d_srcs[p + 1];
        float2 v0 = *(const float2*)&hin[(size_t)s0 * HID + 2 * t];
        float2 v1 = *(const float2*)&hin[(size_t)s1 * HID + 2 * t];
        float4 a00 = al4[p * 2], a01 = al4[p * 2 + 1];
        float4 a10 = al4[p * 2 + 2], a11 = al4[p * 2 + 3];
        float l0[NHEAD] = {a00.x, a00.y, a00.z, a00.w, a01.x, a01.y, a01.z, a01.w};
        float l1[NHEAD] = {a10.x, a10.y, a10.z, a10.w, a11.x, a11.y, a11.z, a11.w};
        #pragma unroll
        for (int i = 0; i < NHEAD; i++) {
            acc[i].x = fmaf(v0.x, l0[i], acc[i].x);
            acc[i].y = fmaf(v0.y, l0[i], acc[i].y);
            acc[i].x = fmaf(v1.x, l1[i], acc[i].x);
            acc[i].y = fmaf(v1.y, l1[i], acc[i].y);
        }
    }
    if (p < end) {
        int s = d_srcs[p];
        float2 v = *(const float2*)&hin[(size_t)s * HID + 2 * t];
        float4 a0 = al4[p * 2], a1 = al4[p * 2 + 1];
        float al[NHEAD] = {a0.x, a0.y, a0.z, a0.w, a1.x, a1.y, a1.z, a1.w};
        #pragma unroll
        for (int i = 0; i < NHEAD; i++) {
            acc[i].x = fmaf(v.x, al[i], acc[i].x);
            acc[i].y = fmaf(v.y, al[i], acc[i].y);
        }
    }
    __half* op = d_aggh + (size_t)nod * KBIG + 2 * t;
    #pragma unroll
    for (int i = 0; i < NHEAD; i++)
        *(__half2*)&op[i * HID] = __floats2half2_rn(acc[i].x, acc[i].y);
}

// ---------------- batch norm ----------------
__device__ __forceinline__ void bn_coeff(int statoff, int c, float& mu, float& rinv) {
    float m = d_bnstat[statoff + c] * (1.f / NN);
    float v = d_bnstat[statoff + c + HID] * (1.f / NN) - m * m;
    mu = m;
    rinv = rsqrtf(v + EPSI);
}

__global__ void bn_partial(const float* __restrict__ x, int statoff) {
    int c = threadIdx.x;
    int nb = gridDim.x;
    int rows = (NN + nb - 1) / nb;
    int r0 = blockIdx.x * rows;
    int r1 = min(NN, r0 + rows);
    float s = 0.f, s2 = 0.f;
    for (int r = r0; r < r1; r++) {
        float v = x[(size_t)r * HID + c];
        s += v; s2 += v * v;
    }
    atomicAdd(&d_bnstat[statoff + c], s);
    atomicAdd(&d_bnstat[statoff + c + HID], s2);
}

__global__ void bn_apply(const float* __restrict__ x,
                         const float* __restrict__ g,
                         const float* __restrict__ be,
                         const float* __restrict__ resid,
                         float* __restrict__ out, int statoff) {
    int i = blockIdx.x * blockDim.x + threadIdx.x;
    if (i >= NN * HID) return;
    int c = i & (HID - 1);
    float mu, rinv;
    bn_coeff(statoff, c, mu, rinv);
    float v = g[c] * (x[i] - mu) * rinv + be[c];
    v = (v > 0.f) ? v : (expf(v) - 1.f);
    if (resid) v += resid[i];
    out[i] = v;
}

__global__ void bn_apply_scores(const float* __restrict__ x,
                                const float* __restrict__ g,
                                const float* __restrict__ be,
                                float* __restrict__ out, int statoff) {
    __shared__ float srow[HID];
    int row = blockIdx.x;
    int t = threadIdx.x;
    int i = row * HID + t;
    float mu, rinv;
    bn_coeff(statoff, t, mu, rinv);
    float v = g[t] * (x[i] - mu) * rinv + be[t];
    v = (v > 0.f) ? v : (expf(v) - 1.f);
    out[i] = v;
    srow[t] = v;
    __syncthreads();
    int head = t >> 5, lane = t & 31;
    float as = 0.f, ad = 0.f;
    #pragma unroll
    for (int cc = 0; cc < HID / 32; cc++) {
        int c2 = cc * 32 + lane;
        float vv = srow[c2];
        as = fmaf(vv, d_wsrc[head * HID + c2], as);
        ad = fmaf(vv, d_wdst[head * HID + c2], ad);
    }
    #pragma unroll
    for (int o = 16; o > 0; o >>= 1) {
        as += __shfl_xor_sync(0xffffffffu, as, o);
        ad += __shfl_xor_sync(0xffffffffu, ad, o);
    }
    if (lane == 0) {
        d_ss[row * NHEAD + head] = as;
        d_sd[row * NHEAD + head] = ad;
    }
}

// ---------------- fp32 split-K GEMM (f32x2, exact; classifier only) ----------------
__global__ __launch_bounds__(256, 2) void gemm128s(const float* __restrict__ A,
                                                   const float* __restrict__ B,
                                                   float* __restrict__ Cpart,
                                                   int M, int Nc, int lda, int ksz) {
    __shared__ float As[2][8][132];
    __shared__ float Bs[2][8][132];

    const int tid  = threadIdx.x;
    const int row0 = blockIdx.y * 128;
    const int col0 = blockIdx.x * 128;
    const int k0   = blockIdx.z * ksz;

    const int arow = tid >> 1;
    const int akg  = (tid & 1) * 4;
    const int bkr  = tid >> 5;
    const int bc4  = (tid & 31) * 4;

    const int lane = tid & 31;
    const int warp = tid >> 5;
    const int m0 = (warp & 3) * 32 + (lane >> 3) * 4;
    const int n0 = (warp >> 2) * 64 + (lane & 7) * 4;

    const int gra = row0 + arow;
    const int gcb = col0 + bc4;

    ull acc[8][4];
    #pragma unroll
    for (int i = 0; i < 8; i++)
        #pragma unroll
        for (int j = 0; j < 4; j++) acc[i][j] = 0ull;

    float aL[4], bL[4];

    auto load_tile = [&](int kabs) {
        if (gra < M) {
            const float4 v = *(const float4*)&A[(size_t)gra * lda + kabs + akg];
            aL[0] = v.x; aL[1] = v.y; aL[2] = v.z; aL[3] = v.w;
        } else {
            aL[0] = aL[1] = aL[2] = aL[3] = 0.f;
        }
        const float* Brow = B + (size_t)(kabs + bkr) * Nc;
        if (gcb + 4 <= Nc) {
            const float4 v = *(const float4*)&Brow[gcb];
            bL[0] = v.x; bL[1] = v.y; bL[2] = v.z; bL[3] = v.w;
        } else {
            #pragma unroll
            for (int i = 0; i < 4; i++)
                bL[i] = (gcb + i < Nc) ? Brow[gcb + i] : 0.f;
        }
    };
    auto store_tile = [&](int buf) {
        #pragma unroll
        for (int i = 0; i < 4; i++) As[buf][akg + i][arow] = aL[i];
        *(float4*)&Bs[buf][bkr][bc4] = make_float4(bL[0], bL[1], bL[2], bL[3]);
    };

    load_tile(k0);
    store_tile(0);
    __syncthreads();

    const int ntiles = ksz >> 3;
    for (int t = 0; t < ntiles; t++) {
        const int buf = t & 1;
        if (t + 1 < ntiles) load_tile(k0 + ((t + 1) << 3));
        #pragma unroll
        for (int k = 0; k < 8; k++) {
            float a_f[8];
            *(float4*)&a_f[0] = *(const float4*)&As[buf][k][m0];
            *(float4*)&a_f[4] = *(const float4*)&As[buf][k][m0 + 16];
            float4 bv0 = *(const float4*)&Bs[buf][k][n0];
            float4 bv1 = *(const float4*)&Bs[buf][k][n0 + 32];
            ull b2[4];
            asm("mov.b64 %0, {%1, %2};" : "=l"(b2[0]) : "f"(bv0.x), "f"(bv0.y));
            asm("mov.b64 %0, {%1, %2};" : "=l"(b2[1]) : "f"(bv0.z), "f"(bv0.w));
            asm("mov.b64 %0, {%1, %2};" : "=l"(b2[2]) : "f"(bv1.x), "f"(bv1.y));
            asm("mov.b64 %0, {%1, %2};" : "=l"(b2[3]) : "f"(bv1.z), "f"(bv1.w));
            #pragma unroll
            for (int i = 0; i < 8; i++) {
                ull a2;
                asm("mov.b64 %0, {%1, %1};" : "=l"(a2) : "f"(a_f[i]));
                #pragma unroll
                for (int j = 0; j < 4; j++)
                    asm("fma.rn.f32x2 %0, %1, %2, %0;"
                        : "+l"(acc[i][j]) : "l"(a2), "l"(b2[j]));
            }
        }
        if (t + 1 < ntiles) {
            store_tile(buf ^ 1);
            __syncthreads();
        }
    }

    float* Cp = Cpart + (size_t)blockIdx.z * M * Nc;
    #pragma unroll
    for (int i = 0; i < 8; i++) {
        const int gm = row0 + ((i < 4) ? (m0 + i) : (m0 + 16 + i - 4));
        if (gm >= M) continue;
        float* Crow = Cp + (size_t)gm * Nc;
        #pragma unroll
        for (int jj = 0; jj < 2; jj++) {
            const int gn = col0 + n0 + jj * 32;
            float v[4];
            asm("mov.b64 {%0, %1}, %2;" : "=f"(v[0]), "=f"(v[1]) : "l"(acc[i][jj * 2]));
            asm("mov.b64 {%0, %1}, %2;" : "=f"(v[2]), "=f"(v[3]) : "l"(acc[i][jj * 2 + 1]));
            if (gn + 4 <= Nc) {
                *(float4*)&Crow[gn] = make_float4(v[0], v[1], v[2], v[3]);
            } else {
                #pragma unroll
                for (int j = 0; j < 4; j++)
                    if (gn + j < Nc) Crow[gn + j] = v[j];
            }
        }
    }
}

// ---------------- fp16 tensor-core GEMM: 3-stage cp.async + ldmatrix + m16n8k16 ----------------
#define GF16_A_STRIDE (128 * 40)
#define GF16_B_STRIDE (32 * 136)
#define GF16_SMEM ((3 * (GF16_A_STRIDE + GF16_B_STRIDE)) * (int)sizeof(__half))

__global__ __launch_bounds__(256, 2) void gemm_f16(const __half* __restrict__ A,
                                                   const __half* __restrict__ B,
                                                   float* __restrict__ Cpart,
                                                   int M, int Nc, int lda, int ksz) {
    extern __shared__ __half sm16[];
    __half* sA = sm16;
    __half* sB = sm16 + 3 * GF16_A_STRIDE;

    const int tid  = threadIdx.x;
    const int row0 = blockIdx.y * 128;
    const int col0 = blockIdx.x * 128;
    const int k0   = blockIdx.z * ksz;
    const int lane = tid & 31;
    const int warp = tid >> 5;
    const int wm   = (warp >> 2) * 64;
    const int wn   = (warp & 3) * 32;

    const int ar = tid >> 1;
    const int ac = (tid & 1) * 16;
    const int br = tid >> 3;
    const int bc = (tid & 7) * 16;

    float c[4][4][4];
    #pragma unroll
    for (int mi = 0; mi < 4; mi++)
        #pragma unroll
        for (int ni = 0; ni < 4; ni++)
            #pragma unroll
            for (int q = 0; q < 4; q++) c[mi][ni][q] = 0.f;

    auto load_stage = [&](int st, int kabs) {
        const __half* ag = A + (size_t)(row0 + ar) * lda + kabs + ac;
        int pa = (row0 + ar < M) ? 16 : 0;
        unsigned sa = (unsigned)__cvta_generic_to_shared(&sA[(st * 128 + ar) * 40 + ac]);
        asm volatile("cp.async.cg.shared.global [%0], [%1], 16, %2;\n" :: "r"(sa), "l"(ag), "r"(pa));
        asm volatile("cp.async.cg.shared.global [%0], [%1], 16, %2;\n" :: "r"(sa + 16), "l"(ag + 8), "r"(pa));
        const __half* bg = B + (size_t)(kabs + br) * Nc + col0 + bc;
        unsigned sb = (unsigned)__cvta_generic_to_shared(&sB[(st * 32 + br) * 136 + bc]);
        asm volatile("cp.async.cg.shared.global [%0], [%1], 16;\n" :: "r"(sb), "l"(bg));
        asm volatile("cp.async.cg.shared.global [%0], [%1], 16;\n" :: "r"(sb + 16), "l"(bg + 8));
        asm volatile("cp.async.commit_group;\n");
    };

    const int nt = ksz >> 5;
    load_stage(0, k0);
    load_stage(1, k0 + 32);
    asm volatile("cp.async.wait_group 1;\n");
    __syncthreads();

    for (int tt = 0; tt < nt; tt++) {
        const int buf = tt % 3;
        #pragma unroll
        for (int kp = 0; kp < 2; kp++) {
            unsigned a[4][4], b[4][2];
            #pragma unroll
            for (int mi = 0; mi < 4; mi++) {
                unsigned ad = (unsigned)__cvta_generic_to_shared(
                    &sA[(buf * 128 + wm + mi * 16 + (lane & 15)) * 40 + kp * 16 + ((lane >> 4) << 3)]);
                asm volatile("ldmatrix.sync.aligned.m8n8.x4.shared.b16 {%0,%1,%2,%3}, [%4];\n"
                             : "=r"(a[mi][0]), "=r"(a[mi][1]), "=r"(a[mi][2]), "=r"(a[mi][3])
                             : "r"(ad));
            }
            #pragma unroll
            for (int ni = 0; ni < 4; ni++) {
                unsigned bd = (unsigned)__cvta_generic_to_shared(
                    &sB[(buf * 32 + kp * 16 + (lane & 15)) * 136 + wn + ni * 8]);
                asm volatile("ldmatrix.sync.aligned.m8n8.x2.trans.shared.b16 {%0,%1}, [%2];\n"
                             : "=r"(b[ni][0]), "=r"(b[ni][1]) : "r"(bd));
            }
            #pragma unroll
            for (int mi = 0; mi < 4; mi++)
                #pragma unroll
                for (int ni = 0; ni < 4; ni++)
                    asm volatile(
                        "mma.sync.aligned.m16n8k16.row.col.f32.f16.f16.f32 "
                        "{%0,%1,%2,%3}, {%4,%5,%6,%7}, {%8,%9}, {%0,%1,%2,%3};\n"
                        : "+f"(c[mi][ni][0]), "+f"(c[mi][ni][1]),
                          "+f"(c[mi][ni][2]), "+f"(c[mi][ni][3])
                        : "r"(a[mi][0]), "r"(a[mi][1]), "r"(a[mi][2]), "r"(a[mi][3]),
                          "r"(b[ni][0]), "r"(b[ni][1]));
        }
        if (tt + 2 < nt) {
            load_stage((tt + 2) % 3, k0 + ((tt + 2) << 5));
            asm volatile("cp.async.wait_group 1;\n");
        } else {
            asm volatile("cp.async.wait_group 0;\n");
        }
        __syncthreads();
    }

    const int g = lane >> 2;
    const int t = lane & 3;
    float* Cp = Cpart + (size_t)blockIdx.z * M * Nc;
    #pragma unroll
    for (int mi = 0; mi < 4; mi++) {
        #pragma unroll
        for (int half = 0; half < 2; half++) {
            const int gm = row0 + wm + mi * 16 + g + half * 8;
            if (gm >= M) continue;
            float* Crow = Cp + (size_t)gm * Nc;
            #pragma unroll
            for (int ni = 0; ni < 4; ni++) {
                const int gn = col0 + wn + ni * 8 + 2 * t;
                float2 v;
                v.x = c[mi][ni][half * 2];
                v.y = c[mi][ni][half * 2 + 1];
                *(float2*)&Crow[gn] = v;
            }
        }
    }
}

// classifier split-4 reduce (+bias)
__global__ void reduce4(const float* __restrict__ part, float* __restrict__ out,
                        const float* __restrict__ bias, float scale, int M, int Nc) {
    int i = blockIdx.x * blockDim.x + threadIdx.x;
    if (i >= M * Nc) return;
    size_t st = (size_t)M * Nc;
    float v = part[i] + part[i + st] + part[i + 2 * st] + part[i + 3 * st];
    v *= scale;
    if (bias) v += bias[i % Nc];
    out[i] = v;
}

// layer-1 split-2 reduce fused with BN stats (streaming; 440 blocks)
__global__ void reduce2_bn(const float* __restrict__ part, float* __restrict__ out,
                           const float* __restrict__ bias, float scale, int statoff) {
    int t = threadIdx.x;
    int nper = (NN + gridDim.x - 1) / gridDim.x;
    int r0 = blockIdx.x * nper;
    int r1 = min(NN, r0 + nper);
    const size_t st = (size_t)NN * HID;
    float b = bias[t];
    float s = 0.f, s2 = 0.f;
    for (int r = r0; r < r1; r++) {
        size_t i = (size_t)r * HID + t;
        float v = part[i] + part[i + st];
        v = v * scale + b;
        out[i] = v;
        s += v;
        s2 += v * v;
    }
    atomicAdd(&d_bnstat[statoff + t], s);
    atomicAdd(&d_bnstat[statoff + t + HID], s2);
}

// layer-0 split-2 reduce fused with attention scores (block = row)
__global__ void reduce2_scores(const float* __restrict__ part, float* __restrict__ out,
                               const float* __restrict__ as0, const float* __restrict__ ad0) {
    int row = blockIdx.x;
    int t = threadIdx.x;
    int i = row * HID + t;
    const size_t st = (size_t)NN * HID;
    float v = part[i] + part[i + st];
    out[i] = v;
    int head = t >> 5, lane = t & 31;
    float ss = v * as0[t];
    float sd = v * ad0[t];
    #pragma unroll
    for (int o = 16; o > 0; o >>= 1) {
        ss += __shfl_xor_sync(0xffffffffu, ss, o);
        sd += __shfl_xor_sync(0xffffffffu, sd, o);
    }
    if (lane == 0) {
        d_ss[row * NHEAD + head] = ss;
        d_sd[row * NHEAD + head] = sd;
    }
}

// ---------------- host launcher ----------------
extern "C" void kernel_launch(void* const* d_in, const int* in_sizes, int n_in,
                              void* d_out, int out_size) {
    (void)in_sizes; (void)n_in; (void)out_size;
    const float* x   = (const float*)d_in[0];
    const int*   ei  = (const int*)d_in[1];
    const float* W0  = (const float*)d_in[2];
    const float* as0 = (const float*)d_in[3];
    const float* ad0 = (const float*)d_in[4];
    const float* b0  = (const float*)d_in[5];
    const float* g0  = (const float*)d_in[6];
    const float* be0 = (const float*)d_in[7];
    const float* W1  = (const float*)d_in[8];
    const float* as1 = (const float*)d_in[9];
    const float* ad1 = (const float*)d_in[10];
    const float* b1  = (const float*)d_in[11];
    const float* g1  = (const float*)d_in[12];
    const float* be1 = (const float*)d_in[13];
    const float* Wc  = (const float*)d_in[14];
    const float* bc  = (const float*)d_in[15];
    float* out = (float*)d_out;
    const int* srcp = ei;
    const int* dstp = ei + EIN;

    static int smem_set = 0;
    if (!smem_set) {
        cudaFuncSetAttribute(gemm_f16, cudaFuncAttributeMaxDynamicSharedMemorySize, GF16_SMEM);
        smem_set = 1;
    }

    void *p_counts;
    void *p_h0, *p_hin, *p_xh, *p_w0h, *p_aggh, *p_w1h, *p_part, *p_h2, *p_out0, *p_out1;
    cudaGetSymbolAddress(&p_counts, d_counts);
    cudaGetSymbolAddress(&p_h0,   d_h0);
    cudaGetSymbolAddress(&p_hin,  d_hin);
    cudaGetSymbolAddress(&p_xh,   d_xh);
    cudaGetSymbolAddress(&p_w0h,  d_w0h);
    cudaGetSymbolAddress(&p_aggh, d_aggh);
    cudaGetSymbolAddress(&p_w1h,  d_w1h);
    cudaGetSymbolAddress(&p_part, d_part);
    cudaGetSymbolAddress(&p_h2,   d_h2);
    cudaGetSymbolAddress(&p_out0, d_out0);
    cudaGetSymbolAddress(&p_out1, d_out1);
    float*  h0   = (float*)p_h0;
    float*  hin  = (float*)p_hin;
    __half* xh   = (__half*)p_xh;
    __half* w0h  = (__half*)p_w0h;
    __half* aggh = (__half*)p_aggh;
    __half* w1h  = (__half*)p_w1h;
    float*  part = (float*)p_part;
    float*  h2   = (float*)p_h2;
    float*  out0 = (float*)p_out0;
    float*  out1 = (float*)p_out1;

    // ---- CSR build + precomputes ----
    cudaMemsetAsync(p_counts, 0, (NN + 1) * sizeof(int));
    count_kernel<<<(ETOT + 255) / 256, 256>>>(dstp);
    scan_kernel<<<1, 1024>>>();
    place_kernel<<<(ETOT + 255) / 256, 256>>>(srcp, dstp);
    prep_kernel<<<(PREP_N1 + PREP_N2 + PREP_N3 + 255) / 256, 256>>>(x, W0, W1, as1, ad1);

    // ---- layer 0 (split-K=2) ----
    gemm_f16<<<dim3(HID / 128, (NN + 127) / 128, 2), 256, GF16_SMEM>>>(xh, w0h, part, NN, HID,
                                                                       HID, HID / 2);
    reduce2_scores<<<NN, HID>>>(part, h0, as0, ad0);
    edge_softmax<<<(NN + 3) / 4, 128>>>();
    aggregate_c32<<<NN, 128>>>(h0, b0, out0);
    bn_partial<<<128, HID>>>(out0, 0);
    bn_apply_scores<<<NN, HID>>>(out0, g0, be0, hin, 0);

    // ---- layer 1 (split-K=2) ----
    edge_softmax<<<(NN + 3) / 4, 128>>>();
    aggregate8<<<NN, 128>>>(hin);
    gemm_f16<<<dim3(HID / 128, (NN + 127) / 128, 2), 256, GF16_SMEM>>>(aggh, w1h, part, NN, HID,
                                                                       KBIG, KBIG / 2);
    reduce2_bn<<<440, HID>>>(part, out1, b1, 1.f / NHEAD, 2 * HID);
    bn_apply<<<(NN * HID + 255) / 256, 256>>>(out1, g1, be1, hin, h2, 2 * HID);

    // ---- classifier (exact f32x2, split-4) ----
    gemm128s<<<dim3(1, (NN + 127) / 128, 4), 256>>>(h2, Wc, part, NN, 40, HID, HID / 4);
    reduce4<<<(NN * 40 + 255) / 256, 256>>>(part, out, bc, 1.f, NN, 40);
}

// round 16
// speedup vs baseline: 1.2832x; 1.0536x over previous
#include <cuda_runtime.h>
#include <cuda_fp16.h>
#include <math.h>

#define NN    10000
#define EIN   160000
#define ETOT  170000
#define NHEAD 8
#define HID   256
#define KBIG  (NHEAD * HID)   // 2048
#define EPSI  1e-5f
#define SLOPE 0.2f
#define CHNK  32

typedef unsigned long long ull;

// ---------------- scratch ----------------
__device__ float  d_h0[NN * HID];
__device__ float  d_hin[NN * HID];
__device__ __half d_xh[NN * HID];
__device__ __half d_w0h[HID * HID];
__device__ __half d_aggh[NN * KBIG];
__device__ __half d_w1h[KBIG * HID];
__device__ float  d_part[4 * NN * HID];
__device__ float  d_out0[NN * HID];
__device__ float  d_out1[NN * HID];
__device__ float  d_h2[NN * HID];
__device__ float  d_ss[NN * NHEAD];
__device__ float  d_sd[NN * NHEAD];
__device__ float  d_wsrc[NHEAD * HID];
__device__ float  d_wdst[NHEAD * HID];
__device__ int    d_counts[NN + 1];
__device__ int    d_offsets[NN + 1];
__device__ int    d_cursor[NN];
__device__ int    d_srcs[ETOT];
__device__ float  d_alpha[ETOT * NHEAD];
__device__ float  d_bnstat[4 * HID];

// ---------------- CSR build (count also zeroes cursor + bnstat) ----------------
__global__ void count_kernel(const int* __restrict__ dst) {
    int i = blockIdx.x * blockDim.x + threadIdx.x;
    if (i < NN) d_cursor[i] = 0;
    if (i < 4 * HID) d_bnstat[i] = 0.f;
    if (i >= ETOT) return;
    int d = (i < EIN) ? dst[i] : (i - EIN);
    atomicAdd(&d_counts[d], 1);
}

__global__ void scan_kernel() {
    __shared__ int sums[1024];
    const int n = NN;
    const int chunk = (n + 1023) / 1024;
    int tid = threadIdx.x;
    int start = tid * chunk;
    int local = 0;
    for (int i = 0; i < chunk; i++)
        if (start + i < n) local += d_counts[start + i];
    sums[tid] = local;
    __syncthreads();
    for (int off = 1; off < 1024; off <<= 1) {
        int v = (tid >= off) ? sums[tid - off] : 0;
        __syncthreads();
        sums[tid] += v;
        __syncthreads();
    }
    int run = (tid == 0) ? 0 : sums[tid - 1];
    for (int i = 0; i < chunk; i++) {
        if (start + i < n) {
            d_offsets[start + i] = run;
            run += d_counts[start + i];
        }
    }
    if (tid == 1023) d_offsets[n] = sums[1023];
}

__global__ void place_kernel(const int* __restrict__ src, const int* __restrict__ dst) {
    int i = blockIdx.x * blockDim.x + threadIdx.x;
    if (i >= ETOT) return;
    int s, d;
    if (i < EIN) { s = src[i]; d = dst[i]; }
    else         { s = d = i - EIN; }
    int pos = d_offsets[d] + atomicAdd(&d_cursor[d], 1);
    d_srcs[pos] = s;
}

// ---------------- prep: conv x/W0 to half + W1 permute-to-half + wtilde ----------------
#define PREP_N1 ((NN * HID + HID * HID) / 4)
#define PREP_N2 (KBIG * (HID / 2))
#define PREP_N3 (NHEAD * HID * 32)
__global__ void prep_kernel(const float* __restrict__ x, const float* __restrict__ W0,
                            const float* __restrict__ W1,
                            const float* __restrict__ as1, const float* __restrict__ ad1) {
    int i = blockIdx.x * blockDim.x + threadIdx.x;
    const int nx = NN * HID / 4;
    if (i < PREP_N1) {
        if (i < nx) {
            const float4 v = ((const float4*)x)[i];
            ((__half2*)d_xh)[i * 2]     = __floats2half2_rn(v.x, v.y);
            ((__half2*)d_xh)[i * 2 + 1] = __floats2half2_rn(v.z, v.w);
        } else {
            int j = i - nx;
            const float4 v = ((const float4*)W0)[j];
            ((__half2*)d_w0h)[j * 2]     = __floats2half2_rn(v.x, v.y);
            ((__half2*)d_w0h)[j * 2 + 1] = __floats2half2_rn(v.z, v.w);
        }
    } else if (i < PREP_N1 + PREP_N2) {
        int j = i - PREP_N1;
        int r = j >> 7;
        int c2 = (j & 127) * 2;
        const float* src = W1 + (size_t)(r & 255) * KBIG + (r >> 8) * HID + c2;
        *(__half2*)&d_w1h[(size_t)r * HID + c2] = __floats2half2_rn(src[0], src[1]);
    } else if (i < PREP_N1 + PREP_N2 + PREP_N3) {
        int j = i - PREP_N1 - PREP_N2;
        int w = j >> 5;
        int lane = j & 31;
        int h = w >> 8;
        int k = w & 255;
        const float* wrow = W1 + (size_t)k * KBIG + h * HID;
        const float* ar = as1 + h * HID;
        const float* dr = ad1 + h * HID;
        float s = 0.f, d = 0.f;
        for (int c = lane; c < HID; c += 32) {
            float wv = wrow[c];
            s = fmaf(wv, ar[c], s);
            d = fmaf(wv, dr[c], d);
        }
        #pragma unroll
        for (int o = 16; o > 0; o >>= 1) {
            s += __shfl_xor_sync(0xffffffffu, s, o);
            d += __shfl_xor_sync(0xffffffffu, d, o);
        }
        if (lane == 0) {
            d_wsrc[w] = s;
            d_wdst[w] = d;
        }
    }
}

// ---------------- per-dst edge softmax (4 warps/block, warp per node) ----------------
__global__ void edge_softmax() {
    int w = (blockIdx.x * blockDim.x + threadIdx.x) >> 5;
    if (w >= NN) return;
    int lane = threadIdx.x & 31;
    int beg = d_offsets[w], end = d_offsets[w + 1];
    const float4* ss4 = (const float4*)d_ss;
    float4* al4 = (float4*)d_alpha;

    float sd[NHEAD];
    #pragma unroll
    for (int h = 0; h < NHEAD; h++) sd[h] = d_sd[w * NHEAD + h];

    float mx[NHEAD];
    #pragma unroll
    for (int h = 0; h < NHEAD; h++) mx[h] = -1e30f;
    for (int p = beg + lane; p < end; p += 32) {
        int s = d_srcs[p];
        float4 v0 = ss4[s * 2], v1 = ss4[s * 2 + 1];
        float sv[NHEAD] = {v0.x, v0.y, v0.z, v0.w, v1.x, v1.y, v1.z, v1.w};
        #pragma unroll
        for (int h = 0; h < NHEAD; h++) {
            float sc = sv[h] + sd[h];
            sc = (sc >= 0.f) ? sc : SLOPE * sc;
            mx[h] = fmaxf(mx[h], sc);
        }
    }
    #pragma unroll
    for (int h = 0; h < NHEAD; h++)
        #pragma unroll
        for (int o = 16; o > 0; o >>= 1)
            mx[h] = fmaxf(mx[h], __shfl_xor_sync(0xffffffffu, mx[h], o));

    float sum[NHEAD];
    #pragma unroll
    for (int h = 0; h < NHEAD; h++) sum[h] = 0.f;
    for (int p = beg + lane; p < end; p += 32) {
        int s = d_srcs[p];
        float4 v0 = ss4[s * 2], v1 = ss4[s * 2 + 1];
        float sv[NHEAD] = {v0.x, v0.y, v0.z, v0.w, v1.x, v1.y, v1.z, v1.w};
        float ev[NHEAD];
        #pragma unroll
        for (int h = 0; h < NHEAD; h++) {
            float sc = sv[h] + sd[h];
            sc = (sc >= 0.f) ? sc : SLOPE * sc;
            float e = __expf(sc - mx[h]);
            sum[h] += e;
            ev[h] = e;
        }
        al4[p * 2]     = make_float4(ev[0], ev[1], ev[2], ev[3]);
        al4[p * 2 + 1] = make_float4(ev[4], ev[5], ev[6], ev[7]);
    }
    #pragma unroll
    for (int h = 0; h < NHEAD; h++)
        #pragma unroll
        for (int o = 16; o > 0; o >>= 1)
            sum[h] += __shfl_xor_sync(0xffffffffu, sum[h], o);

    float r0 = 1.f / sum[0], r1 = 1.f / sum[1], r2 = 1.f / sum[2], r3 = 1.f / sum[3];
    float r4 = 1.f / sum[4], r5 = 1.f / sum[5], r6 = 1.f / sum[6], r7 = 1.f / sum[7];

    for (int p = beg + lane; p < end; p += 32) {
        float4 e0 = al4[p * 2], e1 = al4[p * 2 + 1];
        e0.x *= r0; e0.y *= r1; e0.z *= r2; e0.w *= r3;
        e1.x *= r4; e1.y *= r5; e1.z *= r6; e1.w *= r7;
        al4[p * 2]     = e0;
        al4[p * 2 + 1] = e1;
    }
}

// ---------------- aggregation: 128 threads, float2/thread, smem-staged alphas ----------------
__global__ void aggregate_c32(const float* __restrict__ h,
                              const float* __restrict__ bias,
                              float* __restrict__ out) {
    __shared__ float s_al[CHNK * NHEAD];
    __shared__ int   s_src[CHNK];
    int nod = blockIdx.x;
    int t = threadIdx.x;            // 0..127; channels 2t, 2t+1 (same head)
    int head = t >> 4;
    int beg = d_offsets[nod], end = d_offsets[nod + 1];
    float acc0 = 0.f, acc1 = 0.f;
    for (int c0 = beg; c0 < end; c0 += CHNK) {
        int cnt = min(CHNK, end - c0);
        if (t < cnt) s_src[t] = d_srcs[c0 + t];
        if (t < cnt * 2) ((float4*)s_al)[t] = ((const float4*)d_alpha)[c0 * 2 + t];
        __syncthreads();
        int e = 0;
        for (; e + 2 <= cnt; e += 2) {
            float a0 = s_al[e * NHEAD + head];
            float a1 = s_al[(e + 1) * NHEAD + head];
            float2 v0 = *(const float2*)&h[(size_t)s_src[e] * HID + 2 * t];
            float2 v1 = *(const float2*)&h[(size_t)s_src[e + 1] * HID + 2 * t];
            acc0 = fmaf(v0.x, a0, acc0);
            acc1 = fmaf(v0.y, a0, acc1);
            acc0 = fmaf(v1.x, a1, acc0);
            acc1 = fmaf(v1.y, a1, acc1);
        }
        if (e < cnt) {
            float a = s_al[e * NHEAD + head];
            float2 v = *(const float2*)&h[(size_t)s_src[e] * HID + 2 * t];
            acc0 = fmaf(v.x, a, acc0);
            acc1 = fmaf(v.y, a, acc1);
        }
        __syncthreads();
    }
    float2 b = *(const float2*)&bias[2 * t];
    *(float2*)&out[(size_t)nod * HID + 2 * t] = make_float2(acc0 + b.x, acc1 + b.y);
}

__global__ void aggregate8(const float* __restrict__ hin) {
    __shared__ float s_al[CHNK * NHEAD];
    __shared__ int   s_src[CHNK];
    int nod = blockIdx.x;
    int t = threadIdx.x;            // 0..127; channels 2t, 2t+1
    int beg = d_offsets[nod], end = d_offsets[nod + 1];
    float2 acc[NHEAD];
    #pragma unroll
    for (int i = 0; i < NHEAD; i++) acc[i] = make_float2(0.f, 0.f);
    for (int c0 = beg; c0 < end; c0 += CHNK) {
        int cnt = min(CHNK, end - c0);
        if (t < cnt) s_src[t] = d_srcs[c0 + t];
        if (t < cnt * 2) ((float4*)s_al)[t] = ((const float4*)d_alpha)[c0 * 2 + t];
        __syncthreads();
        int e = 0;
        for (; e + 2 <= cnt; e += 2) {
            float2 v0 = *(const float2*)&hin[(size_t)s_src[e] * HID + 2 * t];
            float2 v1 = *(const float2*)&hin[(size_t)s_src[e + 1] * HID + 2 * t];
            #pragma unroll
            for (int i = 0; i < NHEAD; i++) {
                float a0 = s_al[e * NHEAD + i];
                float a1 = s_al[(e + 1) * NHEAD + i];
                acc[i].x = fmaf(v0.x, a0, acc[i].x);
                acc[i].y = fmaf(v0.y, a0, acc[i].y);
                acc[i].x = fmaf(v1.x, a1, acc[i].x);
                acc[i].y = fmaf(v1.y, a1, acc[i].y);
            }
        }
        if (e < cnt) {
            float2 v = *(const float2*)&hin[(size_t)s_src[e] * HID + 2 * t];
            #pragma unroll
            for (int i = 0; i < NHEAD; i++) {
                float a = s_al[e * NHEAD + i];
                acc[i].x = fmaf(v.x, a, acc[i].x);
                acc[i].y = fmaf(v.y, a, acc[i].y);
            }
        }
        __syncthreads();
    }
    __half* op = d_aggh + (size_t)nod * KBIG + 2 * t;
    #pragma unroll
    for (int i = 0; i < NHEAD; i++)
        *(__half2*)&op[i * HID] = __floats2half2_rn(acc[i].x, acc[i].y);
}

// ---------------- batch norm ----------------
__device__ __forceinline__ void bn_coeff(int statoff, int c, float& mu, float& rinv) {
    float m = d_bnstat[statoff + c] * (1.f / NN);
    float v = d_bnstat[statoff + c + HID] * (1.f / NN) - m * m;
    mu = m;
    rinv = rsqrtf(v + EPSI);
}

__global__ void bn_partial(const float* __restrict__ x, int statoff) {
    int c = threadIdx.x;
    int nb = gridDim.x;
    int rows = (NN + nb - 1) / nb;
    int r0 = blockIdx.x * rows;
    int r1 = min(NN, r0 + rows);
    float s = 0.f, s2 = 0.f;
    for (int r = r0; r < r1; r++) {
        float v = x[(size_t)r * HID + c];
        s += v; s2 += v * v;
    }
    atomicAdd(&d_bnstat[statoff + c], s);
    atomicAdd(&d_bnstat[statoff + c + HID], s2);
}

__global__ void bn_apply(const float* __restrict__ x,
                         const float* __restrict__ g,
                         const float* __restrict__ be,
                         const float* __restrict__ resid,
                         float* __restrict__ out, int statoff) {
    int i = blockIdx.x * blockDim.x + threadIdx.x;
    if (i >= NN * HID) return;
    int c = i & (HID - 1);
    float mu, rinv;
    bn_coeff(statoff, c, mu, rinv);
    float v = g[c] * (x[i] - mu) * rinv + be[c];
    v = (v > 0.f) ? v : (expf(v) - 1.f);
    if (resid) v += resid[i];
    out[i] = v;
}

__global__ void bn_apply_scores(const float* __restrict__ x,
                                const float* __restrict__ g,
                                const float* __restrict__ be,
                                float* __restrict__ out, int statoff) {
    __shared__ float srow[HID];
    int row = blockIdx.x;
    int t = threadIdx.x;
    int i = row * HID + t;
    float mu, rinv;
    bn_coeff(statoff, t, mu, rinv);
    float v = g[t] * (x[i] - mu) * rinv + be[t];
    v = (v > 0.f) ? v : (expf(v) - 1.f);
    out[i] = v;
    srow[t] = v;
    __syncthreads();
    int head = t >> 5, lane = t & 31;
    float as = 0.f, ad = 0.f;
    #pragma unroll
    for (int cc = 0; cc < HID / 32; cc++) {
        int c2 = cc * 32 + lane;
        float vv = srow[c2];
        as = fmaf(vv, d_wsrc[head * HID + c2], as);
        ad = fmaf(vv, d_wdst[head * HID + c2], ad);
    }
    #pragma unroll
    for (int o = 16; o > 0; o >>= 1) {
        as += __shfl_xor_sync(0xffffffffu, as, o);
        ad += __shfl_xor_sync(0xffffffffu, ad, o);
    }
    if (lane == 0) {
        d_ss[row * NHEAD + head] = as;
        d_sd[row * NHEAD + head] = ad;
    }
}

// ---------------- fp32 split-K GEMM (f32x2, exact; classifier only) ----------------
__global__ __launch_bounds__(256, 2) void gemm128s(const float* __restrict__ A,
                                                   const float* __restrict__ B,
                                                   float* __restrict__ Cpart,
                                                   int M, int Nc, int lda, int ksz) {
    __shared__ float As[2][8][132];
    __shared__ float Bs[2][8][132];

    const int tid  = threadIdx.x;
    const int row0 = blockIdx.y * 128;
    const int col0 = blockIdx.x * 128;
    const int k0   = blockIdx.z * ksz;

    const int arow = tid >> 1;
    const int akg  = (tid & 1) * 4;
    const int bkr  = tid >> 5;
    const int bc4  = (tid & 31) * 4;

    const int lane = tid & 31;
    const int warp = tid >> 5;
    const int m0 = (warp & 3) * 32 + (lane >> 3) * 4;
    const int n0 = (warp >> 2) * 64 + (lane & 7) * 4;

    const int gra = row0 + arow;
    const int gcb = col0 + bc4;

    ull acc[8][4];
    #pragma unroll
    for (int i = 0; i < 8; i++)
        #pragma unroll
        for (int j = 0; j < 4; j++) acc[i][j] = 0ull;

    float aL[4], bL[4];

    auto load_tile = [&](int kabs) {
        if (gra < M) {
            const float4 v = *(const float4*)&A[(size_t)gra * lda + kabs + akg];
            aL[0] = v.x; aL[1] = v.y; aL[2] = v.z; aL[3] = v.w;
        } else {
            aL[0] = aL[1] = aL[2] = aL[3] = 0.f;
        }
        const float* Brow = B + (size_t)(kabs + bkr) * Nc;
        if (gcb + 4 <= Nc) {
            const float4 v = *(const float4*)&Brow[gcb];
            bL[0] = v.x; bL[1] = v.y; bL[2] = v.z; bL[3] = v.w;
        } else {
            #pragma unroll
            for (int i = 0; i < 4; i++)
                bL[i] = (gcb + i < Nc) ? Brow[gcb + i] : 0.f;
        }
    };
    auto store_tile = [&](int buf) {
        #pragma unroll
        for (int i = 0; i < 4; i++) As[buf][akg + i][arow] = aL[i];
        *(float4*)&Bs[buf][bkr][bc4] = make_float4(bL[0], bL[1], bL[2], bL[3]);
    };

    load_tile(k0);
    store_tile(0);
    __syncthreads();

    const int ntiles = ksz >> 3;
    for (int t = 0; t < ntiles; t++) {
        const int buf = t & 1;
        if (t + 1 < ntiles) load_tile(k0 + ((t + 1) << 3));
        #pragma unroll
        for (int k = 0; k < 8; k++) {
            float a_f[8];
            *(float4*)&a_f[0] = *(const float4*)&As[buf][k][m0];
            *(float4*)&a_f[4] = *(const float4*)&As[buf][k][m0 + 16];
            float4 bv0 = *(const float4*)&Bs[buf][k][n0];
            float4 bv1 = *(const float4*)&Bs[buf][k][n0 + 32];
            ull b2[4];
            asm("mov.b64 %0, {%1, %2};" : "=l"(b2[0]) : "f"(bv0.x), "f"(bv0.y));
            asm("mov.b64 %0, {%1, %2};" : "=l"(b2[1]) : "f"(bv0.z), "f"(bv0.w));
            asm("mov.b64 %0, {%1, %2};" : "=l"(b2[2]) : "f"(bv1.x), "f"(bv1.y));
            asm("mov.b64 %0, {%1, %2};" : "=l"(b2[3]) : "f"(bv1.z), "f"(bv1.w));
            #pragma unroll
            for (int i = 0; i < 8; i++) {
                ull a2;
                asm("mov.b64 %0, {%1, %1};" : "=l"(a2) : "f"(a_f[i]));
                #pragma unroll
                for (int j = 0; j < 4; j++)
                    asm("fma.rn.f32x2 %0, %1, %2, %0;"
                        : "+l"(acc[i][j]) : "l"(a2), "l"(b2[j]));
            }
        }
        if (t + 1 < ntiles) {
            store_tile(buf ^ 1);
            __syncthreads();
        }
    }

    float* Cp = Cpart + (size_t)blockIdx.z * M * Nc;
    #pragma unroll
    for (int i = 0; i < 8; i++) {
        const int gm = row0 + ((i < 4) ? (m0 + i) : (m0 + 16 + i - 4));
        if (gm >= M) continue;
        float* Crow = Cp + (size_t)gm * Nc;
        #pragma unroll
        for (int jj = 0; jj < 2; jj++) {
            const int gn = col0 + n0 + jj * 32;
            float v[4];
            asm("mov.b64 {%0, %1}, %2;" : "=f"(v[0]), "=f"(v[1]) : "l"(acc[i][jj * 2]));
            asm("mov.b64 {%0, %1}, %2;" : "=f"(v[2]), "=f"(v[3]) : "l"(acc[i][jj * 2 + 1]));
            if (gn + 4 <= Nc) {
                *(float4*)&Crow[gn] = make_float4(v[0], v[1], v[2], v[3]);
            } else {
                #pragma unroll
                for (int j = 0; j < 4; j++)
                    if (gn + j < Nc) Crow[gn + j] = v[j];
            }
        }
    }
}

// ---------------- fp16 tensor-core GEMM: 3-stage cp.async + ldmatrix + m16n8k16 ----------------
#define GF16_A_STRIDE (128 * 40)
#define GF16_B_STRIDE (32 * 136)
#define GF16_SMEM ((3 * (GF16_A_STRIDE + GF16_B_STRIDE)) * (int)sizeof(__half))

__global__ __launch_bounds__(256, 2) void gemm_f16(const __half* __restrict__ A,
                                                   const __half* __restrict__ B,
                                                   float* __restrict__ Cpart,
                                                   int M, int Nc, int lda, int ksz) {
    extern __shared__ __half sm16[];
    __half* sA = sm16;
    __half* sB = sm16 + 3 * GF16_A_STRIDE;

    const int tid  = threadIdx.x;
    const int row0 = blockIdx.y * 128;
    const int col0 = blockIdx.x * 128;
    const int k0   = blockIdx.z * ksz;
    const int lane = tid & 31;
    const int warp = tid >> 5;
    const int wm   = (warp >> 2) * 64;
    const int wn   = (warp & 3) * 32;

    const int ar = tid >> 1;
    const int ac = (tid & 1) * 16;
    const int br = tid >> 3;
    const int bc = (tid & 7) * 16;

    float c[4][4][4];
    #pragma unroll
    for (int mi = 0; mi < 4; mi++)
        #pragma unroll
        for (int ni = 0; ni < 4; ni++)
            #pragma unroll
            for (int q = 0; q < 4; q++) c[mi][ni][q] = 0.f;

    auto load_stage = [&](int st, int kabs) {
        const __half* ag = A + (size_t)(row0 + ar) * lda + kabs + ac;
        int pa = (row0 + ar < M) ? 16 : 0;
        unsigned sa = (unsigned)__cvta_generic_to_shared(&sA[(st * 128 + ar) * 40 + ac]);
        asm volatile("cp.async.cg.shared.global [%0], [%1], 16, %2;\n" :: "r"(sa), "l"(ag), "r"(pa));
        asm volatile("cp.async.cg.shared.global [%0], [%1], 16, %2;\n" :: "r"(sa + 16), "l"(ag + 8), "r"(pa));
        const __half* bg = B + (size_t)(kabs + br) * Nc + col0 + bc;
        unsigned sb = (unsigned)__cvta_generic_to_shared(&sB[(st * 32 + br) * 136 + bc]);
        asm volatile("cp.async.cg.shared.global [%0], [%1], 16;\n" :: "r"(sb), "l"(bg));
        asm volatile("cp.async.cg.shared.global [%0], [%1], 16;\n" :: "r"(sb + 16), "l"(bg + 8));
        asm volatile("cp.async.commit_group;\n");
    };

    const int nt = ksz >> 5;
    load_stage(0, k0);
    load_stage(1, k0 + 32);
    asm volatile("cp.async.wait_group 1;\n");
    __syncthreads();

    for (int tt = 0; tt < nt; tt++) {
        const int buf = tt % 3;
        #pragma unroll
        for (int kp = 0; kp < 2; kp++) {
            unsigned a[4][4], b[4][2];
            #pragma unroll
            for (int mi = 0; mi < 4; mi++) {
                unsigned ad = (unsigned)__cvta_generic_to_shared(
                    &sA[(buf * 128 + wm + mi * 16 + (lane & 15)) * 40 + kp * 16 + ((lane >> 4) << 3)]);
                asm volatile("ldmatrix.sync.aligned.m8n8.x4.shared.b16 {%0,%1,%2,%3}, [%4];\n"
                             : "=r"(a[mi][0]), "=r"(a[mi][1]), "=r"(a[mi][2]), "=r"(a[mi][3])
                             : "r"(ad));
            }
            #pragma unroll
            for (int ni = 0; ni < 4; ni++) {
                unsigned bd = (unsigned)__cvta_generic_to_shared(
                    &sB[(buf * 32 + kp * 16 + (lane & 15)) * 136 + wn + ni * 8]);
                asm volatile("ldmatrix.sync.aligned.m8n8.x2.trans.shared.b16 {%0,%1}, [%2];\n"
                             : "=r"(b[ni][0]), "=r"(b[ni][1]) : "r"(bd));
            }
            #pragma unroll
            for (int mi = 0; mi < 4; mi++)
                #pragma unroll
                for (int ni = 0; ni < 4; ni++)
                    asm volatile(
                        "mma.sync.aligned.m16n8k16.row.col.f32.f16.f16.f32 "
                        "{%0,%1,%2,%3}, {%4,%5,%6,%7}, {%8,%9}, {%0,%1,%2,%3};\n"
                        : "+f"(c[mi][ni][0]), "+f"(c[mi][ni][1]),
                          "+f"(c[mi][ni][2]), "+f"(c[mi][ni][3])
                        : "r"(a[mi][0]), "r"(a[mi][1]), "r"(a[mi][2]), "r"(a[mi][3]),
                          "r"(b[ni][0]), "r"(b[ni][1]));
        }
        if (tt + 2 < nt) {
            load_stage((tt + 2) % 3, k0 + ((tt + 2) << 5));
            asm volatile("cp.async.wait_group 1;\n");
        } else {
            asm volatile("cp.async.wait_group 0;\n");
        }
        __syncthreads();
    }

    const int g = lane >> 2;
    const int t = lane & 3;
    float* Cp = Cpart + (size_t)blockIdx.z * M * Nc;
    #pragma unroll
    for (int mi = 0; mi < 4; mi++) {
        #pragma unroll
        for (int half = 0; half < 2; half++) {
            const int gm = row0 + wm + mi * 16 + g + half * 8;
            if (gm >= M) continue;
            float* Crow = Cp + (size_t)gm * Nc;
            #pragma unroll
            for (int ni = 0; ni < 4; ni++) {
                const int gn = col0 + wn + ni * 8 + 2 * t;
                float2 v;
                v.x = c[mi][ni][half * 2];
                v.y = c[mi][ni][half * 2 + 1];
                *(float2*)&Crow[gn] = v;
            }
        }
    }
}

// classifier split-4 reduce (+bias)
__global__ void reduce4(const float* __restrict__ part, float* __restrict__ out,
                        const float* __restrict__ bias, float scale, int M, int Nc) {
    int i = blockIdx.x * blockDim.x + threadIdx.x;
    if (i >= M * Nc) return;
    size_t st = (size_t)M * Nc;
    float v = part[i] + part[i + st] + part[i + 2 * st] + part[i + 3 * st];
    v *= scale;
    if (bias) v += bias[i % Nc];
    out[i] = v;
}

// layer-1 split-2 reduce fused with BN stats (streaming; 440 blocks)
__global__ void reduce2_bn(const float* __restrict__ part, float* __restrict__ out,
                           const float* __restrict__ bias, float scale, int statoff) {
    int t = threadIdx.x;
    int nper = (NN + gridDim.x - 1) / gridDim.x;
    int r0 = blockIdx.x * nper;
    int r1 = min(NN, r0 + nper);
    const size_t st = (size_t)NN * HID;
    float b = bias[t];
    float s = 0.f, s2 = 0.f;
    for (int r = r0; r < r1; r++) {
        size_t i = (size_t)r * HID + t;
        float v = part[i] + part[i + st];
        v = v * scale + b;
        out[i] = v;
        s += v;
        s2 += v * v;
    }
    atomicAdd(&d_bnstat[statoff + t], s);
    atomicAdd(&d_bnstat[statoff + t + HID], s2);
}

// layer-0 split-2 reduce fused with attention scores (block = row)
__global__ void reduce2_scores(const float* __restrict__ part, float* __restrict__ out,
                               const float* __restrict__ as0, const float* __restrict__ ad0) {
    int row = blockIdx.x;
    int t = threadIdx.x;
    int i = row * HID + t;
    const size_t st = (size_t)NN * HID;
    float v = part[i] + part[i + st];
    out[i] = v;
    int head = t >> 5, lane = t & 31;
    float ss = v * as0[t];
    float sd = v * ad0[t];
    #pragma unroll
    for (int o = 16; o > 0; o >>= 1) {
        ss += __shfl_xor_sync(0xffffffffu, ss, o);
        sd += __shfl_xor_sync(0xffffffffu, sd, o);
    }
    if (lane == 0) {
        d_ss[row * NHEAD + head] = ss;
        d_sd[row * NHEAD + head] = sd;
    }
}

// ---------------- host launcher ----------------
extern "C" void kernel_launch(void* const* d_in, const int* in_sizes, int n_in,
                              void* d_out, int out_size) {
    (void)in_sizes; (void)n_in; (void)out_size;
    const float* x   = (const float*)d_in[0];
    const int*   ei  = (const int*)d_in[1];
    const float* W0  = (const float*)d_in[2];
    const float* as0 = (const float*)d_in[3];
    const float* ad0 = (const float*)d_in[4];
    const float* b0  = (const float*)d_in[5];
    const float* g0  = (const float*)d_in[6];
    const float* be0 = (const float*)d_in[7];
    const float* W1  = (const float*)d_in[8];
    const float* as1 = (const float*)d_in[9];
    const float* ad1 = (const float*)d_in[10];
    const float* b1  = (const float*)d_in[11];
    const float* g1  = (const float*)d_in[12];
    const float* be1 = (const float*)d_in[13];
    const float* Wc  = (const float*)d_in[14];
    const float* bc  = (const float*)d_in[15];
    float* out = (float*)d_out;
    const int* srcp = ei;
    const int* dstp = ei + EIN;

    static int smem_set = 0;
    if (!smem_set) {
        cudaFuncSetAttribute(gemm_f16, cudaFuncAttributeMaxDynamicSharedMemorySize, GF16_SMEM);
        smem_set = 1;
    }

    void *p_counts;
    void *p_h0, *p_hin, *p_xh, *p_w0h, *p_aggh, *p_w1h, *p_part, *p_h2, *p_out0, *p_out1;
    cudaGetSymbolAddress(&p_counts, d_counts);
    cudaGetSymbolAddress(&p_h0,   d_h0);
    cudaGetSymbolAddress(&p_hin,  d_hin);
    cudaGetSymbolAddress(&p_xh,   d_xh);
    cudaGetSymbolAddress(&p_w0h,  d_w0h);
    cudaGetSymbolAddress(&p_aggh, d_aggh);
    cudaGetSymbolAddress(&p_w1h,  d_w1h);
    cudaGetSymbolAddress(&p_part, d_part);
    cudaGetSymbolAddress(&p_h2,   d_h2);
    cudaGetSymbolAddress(&p_out0, d_out0);
    cudaGetSymbolAddress(&p_out1, d_out1);
    float*  h0   = (float*)p_h0;
    float*  hin  = (float*)p_hin;
    __half* xh   = (__half*)p_xh;
    __half* w0h  = (__half*)p_w0h;
    __half* aggh = (__half*)p_aggh;
    __half* w1h  = (__half*)p_w1h;
    float*  part = (float*)p_part;
    float*  h2   = (float*)p_h2;
    float*  out0 = (float*)p_out0;
    float*  out1 = (float*)p_out1;

    // ---- CSR build + precomputes ----
    cudaMemsetAsync(p_counts, 0, (NN + 1) * sizeof(int));
    count_kernel<<<(ETOT + 255) / 256, 256>>>(dstp);
    scan_kernel<<<1, 1024>>>();
    place_kernel<<<(ETOT + 255) / 256, 256>>>(srcp, dstp);
    prep_kernel<<<(PREP_N1 + PREP_N2 + PREP_N3 + 255) / 256, 256>>>(x, W0, W1, as1, ad1);

    // ---- layer 0 (split-K=2) ----
    gemm_f16<<<dim3(HID / 128, (NN + 127) / 128, 2), 256, GF16_SMEM>>>(xh, w0h, part, NN, HID,
                                                                       HID, HID / 2);
    reduce2_scores<<<NN, HID>>>(part, h0, as0, ad0);
    edge_softmax<<<(NN + 3) / 4, 128>>>();
    aggregate_c32<<<NN, 128>>>(h0, b0, out0);
    bn_partial<<<128, HID>>>(out0, 0);
    bn_apply_scores<<<NN, HID>>>(out0, g0, be0, hin, 0);

    // ---- layer 1 (split-K=2) ----
    edge_softmax<<<(NN + 3) / 4, 128>>>();
    aggregate8<<<NN, 128>>>(hin);
    gemm_f16<<<dim3(HID / 128, (NN + 127) / 128, 2), 256, GF16_SMEM>>>(aggh, w1h, part, NN, HID,
                                                                       KBIG, KBIG / 2);
    reduce2_bn<<<440, HID>>>(part, out1, b1, 1.f / NHEAD, 2 * HID);
    bn_apply<<<(NN * HID + 255) / 256, 256>>>(out1, g1, be1, hin, h2, 2 * HID);

    // ---- classifier (exact f32x2, split-4) ----
    gemm128s<<<dim3(1, (NN + 127) / 128, 4), 256>>>(h2, Wc, part, NN, 40, HID, HID / 4);
    reduce4<<<(NN * 40 + 255) / 256, 256>>>(part, out, bc, 1.f, NN, 40);
}

// round 17
// speedup vs baseline: 1.2870x; 1.0030x over previous
#include <cuda_runtime.h>
#include <cuda_fp16.h>
#include <math.h>

#define NN    10000
#define EIN   160000
#define ETOT  170000
#define NHEAD 8
#define HID   256
#define KBIG  (NHEAD * HID)   // 2048
#define EPSI  1e-5f
#define SLOPE 0.2f
#define CHNK  32

typedef unsigned long long ull;

// ---------------- scratch ----------------
__device__ float  d_h0[NN * HID];
__device__ float  d_hin[NN * HID];
__device__ __half d_xh[NN * HID];
__device__ __half d_w0h[HID * HID];
__device__ __half d_aggh[NN * KBIG];
__device__ __half d_w1h[KBIG * HID];
__device__ float  d_part[4 * NN * HID];
__device__ float  d_out0[NN * HID];
__device__ float  d_out1[NN * HID];
__device__ float  d_h2[NN * HID];
__device__ float  d_ss[NN * NHEAD];
__device__ float  d_sd[NN * NHEAD];   // scores pre-softmax; 1/sum post-softmax
__device__ float  d_wsrc[NHEAD * HID];
__device__ float  d_wdst[NHEAD * HID];
__device__ int    d_counts[NN + 1];
__device__ int    d_offsets[NN + 1];
__device__ int    d_cursor[NN];
__device__ int    d_srcs[ETOT];
__device__ float  d_alpha[ETOT * NHEAD];
__device__ float  d_bnstat[4 * HID];

// ---------------- CSR build (count also zeroes cursor + bnstat) ----------------
__global__ void count_kernel(const int* __restrict__ dst) {
    int i = blockIdx.x * blockDim.x + threadIdx.x;
    if (i < NN) d_cursor[i] = 0;
    if (i < 4 * HID) d_bnstat[i] = 0.f;
    if (i >= ETOT) return;
    int d = (i < EIN) ? dst[i] : (i - EIN);
    atomicAdd(&d_counts[d], 1);
}

__global__ void scan_kernel() {
    __shared__ int sums[1024];
    const int n = NN;
    const int chunk = (n + 1023) / 1024;
    int tid = threadIdx.x;
    int start = tid * chunk;
    int local = 0;
    for (int i = 0; i < chunk; i++)
        if (start + i < n) local += d_counts[start + i];
    sums[tid] = local;
    __syncthreads();
    for (int off = 1; off < 1024; off <<= 1) {
        int v = (tid >= off) ? sums[tid - off] : 0;
        __syncthreads();
        sums[tid] += v;
        __syncthreads();
    }
    int run = (tid == 0) ? 0 : sums[tid - 1];
    for (int i = 0; i < chunk; i++) {
        if (start + i < n) {
            d_offsets[start + i] = run;
            run += d_counts[start + i];
        }
    }
    if (tid == 1023) d_offsets[n] = sums[1023];
}

__global__ void place_kernel(const int* __restrict__ src, const int* __restrict__ dst) {
    int i = blockIdx.x * blockDim.x + threadIdx.x;
    if (i >= ETOT) return;
    int s, d;
    if (i < EIN) { s = src[i]; d = dst[i]; }
    else         { s = d = i - EIN; }
    int pos = d_offsets[d] + atomicAdd(&d_cursor[d], 1);
    d_srcs[pos] = s;
}

// ---------------- prep: conv x/W0 to half + W1 permute-to-half + wtilde ----------------
#define PREP_N1 ((NN * HID + HID * HID) / 4)
#define PREP_N2 (KBIG * (HID / 2))
#define PREP_N3 (NHEAD * HID * 32)
__global__ void prep_kernel(const float* __restrict__ x, const float* __restrict__ W0,
                            const float* __restrict__ W1,
                            const float* __restrict__ as1, const float* __restrict__ ad1) {
    int i = blockIdx.x * blockDim.x + threadIdx.x;
    const int nx = NN * HID / 4;
    if (i < PREP_N1) {
        if (i < nx) {
            const float4 v = ((const float4*)x)[i];
            ((__half2*)d_xh)[i * 2]     = __floats2half2_rn(v.x, v.y);
            ((__half2*)d_xh)[i * 2 + 1] = __floats2half2_rn(v.z, v.w);
        } else {
            int j = i - nx;
            const float4 v = ((const float4*)W0)[j];
            ((__half2*)d_w0h)[j * 2]     = __floats2half2_rn(v.x, v.y);
            ((__half2*)d_w0h)[j * 2 + 1] = __floats2half2_rn(v.z, v.w);
        }
    } else if (i < PREP_N1 + PREP_N2) {
        int j = i - PREP_N1;
        int r = j >> 7;
        int c2 = (j & 127) * 2;
        const float* src = W1 + (size_t)(r & 255) * KBIG + (r >> 8) * HID + c2;
        *(__half2*)&d_w1h[(size_t)r * HID + c2] = __floats2half2_rn(src[0], src[1]);
    } else if (i < PREP_N1 + PREP_N2 + PREP_N3) {
        int j = i - PREP_N1 - PREP_N2;
        int w = j >> 5;
        int lane = j & 31;
        int h = w >> 8;
        int k = w & 255;
        const float* wrow = W1 + (size_t)k * KBIG + h * HID;
        const float* ar = as1 + h * HID;
        const float* dr = ad1 + h * HID;
        float s = 0.f, d = 0.f;
        for (int c = lane; c < HID; c += 32) {
            float wv = wrow[c];
            s = fmaf(wv, ar[c], s);
            d = fmaf(wv, dr[c], d);
        }
        #pragma unroll
        for (int o = 16; o > 0; o >>= 1) {
            s += __shfl_xor_sync(0xffffffffu, s, o);
            d += __shfl_xor_sync(0xffffffffu, d, o);
        }
        if (lane == 0) {
            d_wsrc[w] = s;
            d_wdst[w] = d;
        }
    }
}

// ---------------- per-dst edge softmax: 1 gather pass + 1 linear pass ----------------
// pass1: gather ss, leaky, STORE score to alpha, max
// pass2: linear read alpha, exp, sum, store e; 1/sum -> d_sd (consumed by aggregates)
__global__ void edge_softmax() {
    int w = (blockIdx.x * blockDim.x + threadIdx.x) >> 5;
    if (w >= NN) return;
    int lane = threadIdx.x & 31;
    int beg = d_offsets[w], end = d_offsets[w + 1];
    const float4* ss4 = (const float4*)d_ss;
    float4* al4 = (float4*)d_alpha;

    float sd[NHEAD];
    #pragma unroll
    for (int h = 0; h < NHEAD; h++) sd[h] = d_sd[w * NHEAD + h];

    float mx[NHEAD];
    #pragma unroll
    for (int h = 0; h < NHEAD; h++) mx[h] = -1e30f;
    for (int p = beg + lane; p < end; p += 32) {
        int s = d_srcs[p];
        float4 v0 = ss4[s * 2], v1 = ss4[s * 2 + 1];
        float sv[NHEAD] = {v0.x, v0.y, v0.z, v0.w, v1.x, v1.y, v1.z, v1.w};
        float sc[NHEAD];
        #pragma unroll
        for (int h = 0; h < NHEAD; h++) {
            float v = sv[h] + sd[h];
            v = (v >= 0.f) ? v : SLOPE * v;
            sc[h] = v;
            mx[h] = fmaxf(mx[h], v);
        }
        al4[p * 2]     = make_float4(sc[0], sc[1], sc[2], sc[3]);
        al4[p * 2 + 1] = make_float4(sc[4], sc[5], sc[6], sc[7]);
    }
    #pragma unroll
    for (int h = 0; h < NHEAD; h++)
        #pragma unroll
        for (int o = 16; o > 0; o >>= 1)
            mx[h] = fmaxf(mx[h], __shfl_xor_sync(0xffffffffu, mx[h], o));

    float sum[NHEAD];
    #pragma unroll
    for (int h = 0; h < NHEAD; h++) sum[h] = 0.f;
    for (int p = beg + lane; p < end; p += 32) {
        float4 s0 = al4[p * 2], s1 = al4[p * 2 + 1];
        float sc[NHEAD] = {s0.x, s0.y, s0.z, s0.w, s1.x, s1.y, s1.z, s1.w};
        float ev[NHEAD];
        #pragma unroll
        for (int h = 0; h < NHEAD; h++) {
            float e = __expf(sc[h] - mx[h]);
            sum[h] += e;
            ev[h] = e;
        }
        al4[p * 2]     = make_float4(ev[0], ev[1], ev[2], ev[3]);
        al4[p * 2 + 1] = make_float4(ev[4], ev[5], ev[6], ev[7]);
    }
    #pragma unroll
    for (int h = 0; h < NHEAD; h++)
        #pragma unroll
        for (int o = 16; o > 0; o >>= 1)
            sum[h] += __shfl_xor_sync(0xffffffffu, sum[h], o);

    if (lane < NHEAD)
        d_sd[w * NHEAD + lane] = 1.f / sum[lane];
}

// ---------------- aggregation: smem-staged alphas scaled by 1/sum during staging ----------------
__global__ void aggregate_c32(const float* __restrict__ h,
                              const float* __restrict__ bias,
                              float* __restrict__ out) {
    __shared__ float s_al[CHNK * NHEAD];
    __shared__ float s_rs[NHEAD];
    __shared__ int   s_src[CHNK];
    int nod = blockIdx.x;
    int t = threadIdx.x;            // 0..127; channels 2t, 2t+1 (same head)
    int head = t >> 4;
    int beg = d_offsets[nod], end = d_offsets[nod + 1];
    if (t < NHEAD) s_rs[t] = d_sd[nod * NHEAD + t];
    __syncthreads();
    float acc0 = 0.f, acc1 = 0.f;
    for (int c0 = beg; c0 < end; c0 += CHNK) {
        int cnt = min(CHNK, end - c0);
        if (t < cnt) s_src[t] = d_srcs[c0 + t];
        if (t < cnt * 2) {
            float4 v = ((const float4*)d_alpha)[c0 * 2 + t];
            int hb = (t & 1) * 4;
            v.x *= s_rs[hb]; v.y *= s_rs[hb + 1]; v.z *= s_rs[hb + 2]; v.w *= s_rs[hb + 3];
            ((float4*)s_al)[t] = v;
        }
        __syncthreads();
        int e = 0;
        for (; e + 2 <= cnt; e += 2) {
            float a0 = s_al[e * NHEAD + head];
            float a1 = s_al[(e + 1) * NHEAD + head];
            float2 v0 = *(const float2*)&h[(size_t)s_src[e] * HID + 2 * t];
            float2 v1 = *(const float2*)&h[(size_t)s_src[e + 1] * HID + 2 * t];
            acc0 = fmaf(v0.x, a0, acc0);
            acc1 = fmaf(v0.y, a0, acc1);
            acc0 = fmaf(v1.x, a1, acc0);
            acc1 = fmaf(v1.y, a1, acc1);
        }
        if (e < cnt) {
            float a = s_al[e * NHEAD + head];
            float2 v = *(const float2*)&h[(size_t)s_src[e] * HID + 2 * t];
            acc0 = fmaf(v.x, a, acc0);
            acc1 = fmaf(v.y, a, acc1);
        }
        __syncthreads();
    }
    float2 b = *(const float2*)&bias[2 * t];
    *(float2*)&out[(size_t)nod * HID + 2 * t] = make_float2(acc0 + b.x, acc1 + b.y);
}

__global__ void aggregate8(const float* __restrict__ hin) {
    __shared__ float s_al[CHNK * NHEAD];
    __shared__ float s_rs[NHEAD];
    __shared__ int   s_src[CHNK];
    int nod = blockIdx.x;
    int t = threadIdx.x;            // 0..127; channels 2t, 2t+1
    int beg = d_offsets[nod], end = d_offsets[nod + 1];
    if (t < NHEAD) s_rs[t] = d_sd[nod * NHEAD + t];
    __syncthreads();
    float2 acc[NHEAD];
    #pragma unroll
    for (int i = 0; i < NHEAD; i++) acc[i] = make_float2(0.f, 0.f);
    for (int c0 = beg; c0 < end; c0 += CHNK) {
        int cnt = min(CHNK, end - c0);
        if (t < cnt) s_src[t] = d_srcs[c0 + t];
        if (t < cnt * 2) {
            float4 v = ((const float4*)d_alpha)[c0 * 2 + t];
            int hb = (t & 1) * 4;
            v.x *= s_rs[hb]; v.y *= s_rs[hb + 1]; v.z *= s_rs[hb + 2]; v.w *= s_rs[hb + 3];
            ((float4*)s_al)[t] = v;
        }
        __syncthreads();
        int e = 0;
        for (; e + 2 <= cnt; e += 2) {
            float2 v0 = *(const float2*)&hin[(size_t)s_src[e] * HID + 2 * t];
            float2 v1 = *(const float2*)&hin[(size_t)s_src[e + 1] * HID + 2 * t];
            #pragma unroll
            for (int i = 0; i < NHEAD; i++) {
                float a0 = s_al[e * NHEAD + i];
                float a1 = s_al[(e + 1) * NHEAD + i];
                acc[i].x = fmaf(v0.x, a0, acc[i].x);
                acc[i].y = fmaf(v0.y, a0, acc[i].y);
                acc[i].x = fmaf(v1.x, a1, acc[i].x);
                acc[i].y = fmaf(v1.y, a1, acc[i].y);
            }
        }
        if (e < cnt) {
            float2 v = *(const float2*)&hin[(size_t)s_src[e] * HID + 2 * t];
            #pragma unroll
            for (int i = 0; i < NHEAD; i++) {
                float a = s_al[e * NHEAD + i];
                acc[i].x = fmaf(v.x, a, acc[i].x);
                acc[i].y = fmaf(v.y, a, acc[i].y);
            }
        }
        __syncthreads();
    }
    __half* op = d_aggh + (size_t)nod * KBIG + 2 * t;
    #pragma unroll
    for (int i = 0; i < NHEAD; i++)
        *(__half2*)&op[i * HID] = __floats2half2_rn(acc[i].x, acc[i].y);
}

// ---------------- batch norm ----------------
__device__ __forceinline__ void bn_coeff(int statoff, int c, float& mu, float& rinv) {
    float m = d_bnstat[statoff + c] * (1.f / NN);
    float v = d_bnstat[statoff + c + HID] * (1.f / NN) - m * m;
    mu = m;
    rinv = rsqrtf(v + EPSI);
}

__global__ void bn_partial(const float* __restrict__ x, int statoff) {
    int c = threadIdx.x;
    int nb = gridDim.x;
    int rows = (NN + nb - 1) / nb;
    int r0 = blockIdx.x * rows;
    int r1 = min(NN, r0 + rows);
    float s = 0.f, s2 = 0.f;
    for (int r = r0; r < r1; r++) {
        float v = x[(size_t)r * HID + c];
        s += v; s2 += v * v;
    }
    atomicAdd(&d_bnstat[statoff + c], s);
    atomicAdd(&d_bnstat[statoff + c + HID], s2);
}

__global__ void bn_apply(const float* __restrict__ x,
                         const float* __restrict__ g,
                         const float* __restrict__ be,
                         const float* __restrict__ resid,
                         float* __restrict__ out, int statoff) {
    int i = blockIdx.x * blockDim.x + threadIdx.x;
    if (i >= NN * HID) return;
    int c = i & (HID - 1);
    float mu, rinv;
    bn_coeff(statoff, c, mu, rinv);
    float v = g[c] * (x[i] - mu) * rinv + be[c];
    v = (v > 0.f) ? v : (expf(v) - 1.f);
    if (resid) v += resid[i];
    out[i] = v;
}

__global__ void bn_apply_scores(const float* __restrict__ x,
                                const float* __restrict__ g,
                                const float* __restrict__ be,
                                float* __restrict__ out, int statoff) {
    __shared__ float srow[HID];
    int row = blockIdx.x;
    int t = threadIdx.x;
    int i = row * HID + t;
    float mu, rinv;
    bn_coeff(statoff, t, mu, rinv);
    float v = g[t] * (x[i] - mu) * rinv + be[t];
    v = (v > 0.f) ? v : (expf(v) - 1.f);
    out[i] = v;
    srow[t] = v;
    __syncthreads();
    int head = t >> 5, lane = t & 31;
    float as = 0.f, ad = 0.f;
    #pragma unroll
    for (int cc = 0; cc < HID / 32; cc++) {
        int c2 = cc * 32 + lane;
        float vv = srow[c2];
        as = fmaf(vv, d_wsrc[head * HID + c2], as);
        ad = fmaf(vv, d_wdst[head * HID + c2], ad);
    }
    #pragma unroll
    for (int o = 16; o > 0; o >>= 1) {
        as += __shfl_xor_sync(0xffffffffu, as, o);
        ad += __shfl_xor_sync(0xffffffffu, ad, o);
    }
    if (lane == 0) {
        d_ss[row * NHEAD + head] = as;
        d_sd[row * NHEAD + head] = ad;
    }
}

// ---------------- fp32 split-K GEMM (f32x2, exact; classifier only) ----------------
__global__ __launch_bounds__(256, 2) void gemm128s(const float* __restrict__ A,
                                                   const float* __restrict__ B,
                                                   float* __restrict__ Cpart,
                                                   int M, int Nc, int lda, int ksz) {
    __shared__ float As[2][8][132];
    __shared__ float Bs[2][8][132];

    const int tid  = threadIdx.x;
    const int row0 = blockIdx.y * 128;
    const int col0 = blockIdx.x * 128;
    const int k0   = blockIdx.z * ksz;

    const int arow = tid >> 1;
    const int akg  = (tid & 1) * 4;
    const int bkr  = tid >> 5;
    const int bc4  = (tid & 31) * 4;

    const int lane = tid & 31;
    const int warp = tid >> 5;
    const int m0 = (warp & 3) * 32 + (lane >> 3) * 4;
    const int n0 = (warp >> 2) * 64 + (lane & 7) * 4;

    const int gra = row0 + arow;
    const int gcb = col0 + bc4;

    ull acc[8][4];
    #pragma unroll
    for (int i = 0; i < 8; i++)
        #pragma unroll
        for (int j = 0; j < 4; j++) acc[i][j] = 0ull;

    float aL[4], bL[4];

    auto load_tile = [&](int kabs) {
        if (gra < M) {
            const float4 v = *(const float4*)&A[(size_t)gra * lda + kabs + akg];
            aL[0] = v.x; aL[1] = v.y; aL[2] = v.z; aL[3] = v.w;
        } else {
            aL[0] = aL[1] = aL[2] = aL[3] = 0.f;
        }
        const float* Brow = B + (size_t)(kabs + bkr) * Nc;
        if (gcb + 4 <= Nc) {
            const float4 v = *(const float4*)&Brow[gcb];
            bL[0] = v.x; bL[1] = v.y; bL[2] = v.z; bL[3] = v.w;
        } else {
            #pragma unroll
            for (int i = 0; i < 4; i++)
                bL[i] = (gcb + i < Nc) ? Brow[gcb + i] : 0.f;
        }
    };
    auto store_tile = [&](int buf) {
        #pragma unroll
        for (int i = 0; i < 4; i++) As[buf][akg + i][arow] = aL[i];
        *(float4*)&Bs[buf][bkr][bc4] = make_float4(bL[0], bL[1], bL[2], bL[3]);
    };

    load_tile(k0);
    store_tile(0);
    __syncthreads();

    const int ntiles = ksz >> 3;
    for (int t = 0; t < ntiles; t++) {
        const int buf = t & 1;
        if (t + 1 < ntiles) load_tile(k0 + ((t + 1) << 3));
        #pragma unroll
        for (int k = 0; k < 8; k++) {
            float a_f[8];
            *(float4*)&a_f[0] = *(const float4*)&As[buf][k][m0];
            *(float4*)&a_f[4] = *(const float4*)&As[buf][k][m0 + 16];
            float4 bv0 = *(const float4*)&Bs[buf][k][n0];
            float4 bv1 = *(const float4*)&Bs[buf][k][n0 + 32];
            ull b2[4];
            asm("mov.b64 %0, {%1, %2};" : "=l"(b2[0]) : "f"(bv0.x), "f"(bv0.y));
            asm("mov.b64 %0, {%1, %2};" : "=l"(b2[1]) : "f"(bv0.z), "f"(bv0.w));
            asm("mov.b64 %0, {%1, %2};" : "=l"(b2[2]) : "f"(bv1.x), "f"(bv1.y));
            asm("mov.b64 %0, {%1, %2};" : "=l"(b2[3]) : "f"(bv1.z), "f"(bv1.w));
            #pragma unroll
            for (int i = 0; i < 8; i++) {
                ull a2;
                asm("mov.b64 %0, {%1, %1};" : "=l"(a2) : "f"(a_f[i]));
                #pragma unroll
                for (int j = 0; j < 4; j++)
                    asm("fma.rn.f32x2 %0, %1, %2, %0;"
                        : "+l"(acc[i][j]) : "l"(a2), "l"(b2[j]));
            }
        }
        if (t + 1 < ntiles) {
            store_tile(buf ^ 1);
            __syncthreads();
        }
    }

    float* Cp = Cpart + (size_t)blockIdx.z * M * Nc;
    #pragma unroll
    for (int i = 0; i < 8; i++) {
        const int gm = row0 + ((i < 4) ? (m0 + i) : (m0 + 16 + i - 4));
        if (gm >= M) continue;
        float* Crow = Cp + (size_t)gm * Nc;
        #pragma unroll
        for (int jj = 0; jj < 2; jj++) {
            const int gn = col0 + n0 + jj * 32;
            float v[4];
            asm("mov.b64 {%0, %1}, %2;" : "=f"(v[0]), "=f"(v[1]) : "l"(acc[i][jj * 2]));
            asm("mov.b64 {%0, %1}, %2;" : "=f"(v[2]), "=f"(v[3]) : "l"(acc[i][jj * 2 + 1]));
            if (gn + 4 <= Nc) {
                *(float4*)&Crow[gn] = make_float4(v[0], v[1], v[2], v[3]);
            } else {
                #pragma unroll
                for (int j = 0; j < 4; j++)
                    if (gn + j < Nc) Crow[gn + j] = v[j];
            }
        }
    }
}

// ---------------- fp16 tensor-core GEMM: 3-stage cp.async + ldmatrix + m16n8k16 ----------------
#define GF16_A_STRIDE (128 * 40)
#define GF16_B_STRIDE (32 * 136)
#define GF16_SMEM ((3 * (GF16_A_STRIDE + GF16_B_STRIDE)) * (int)sizeof(__half))

__global__ __launch_bounds__(256, 2) void gemm_f16(const __half* __restrict__ A,
                                                   const __half* __restrict__ B,
                                                   float* __restrict__ Cpart,
                                                   int M, int Nc, int lda, int ksz) {
    extern __shared__ __half sm16[];
    __half* sA = sm16;
    __half* sB = sm16 + 3 * GF16_A_STRIDE;

    const int tid  = threadIdx.x;
    const int row0 = blockIdx.y * 128;
    const int col0 = blockIdx.x * 128;
    const int k0   = blockIdx.z * ksz;
    const int lane = tid & 31;
    const int warp = tid >> 5;
    const int wm   = (warp >> 2) * 64;
    const int wn   = (warp & 3) * 32;

    const int ar = tid >> 1;
    const int ac = (tid & 1) * 16;
    const int br = tid >> 3;
    const int bc = (tid & 7) * 16;

    float c[4][4][4];
    #pragma unroll
    for (int mi = 0; mi < 4; mi++)
        #pragma unroll
        for (int ni = 0; ni < 4; ni++)
            #pragma unroll
            for (int q = 0; q < 4; q++) c[mi][ni][q] = 0.f;

    auto load_stage = [&](int st, int kabs) {
        const __half* ag = A + (size_t)(row0 + ar) * lda + kabs + ac;
        int pa = (row0 + ar < M) ? 16 : 0;
        unsigned sa = (unsigned)__cvta_generic_to_shared(&sA[(st * 128 + ar) * 40 + ac]);
        asm volatile("cp.async.cg.shared.global [%0], [%1], 16, %2;\n" :: "r"(sa), "l"(ag), "r"(pa));
        asm volatile("cp.async.cg.shared.global [%0], [%1], 16, %2;\n" :: "r"(sa + 16), "l"(ag + 8), "r"(pa));
        const __half* bg = B + (size_t)(kabs + br) * Nc + col0 + bc;
        unsigned sb = (unsigned)__cvta_generic_to_shared(&sB[(st * 32 + br) * 136 + bc]);
        asm volatile("cp.async.cg.shared.global [%0], [%1], 16;\n" :: "r"(sb), "l"(bg));
        asm volatile("cp.async.cg.shared.global [%0], [%1], 16;\n" :: "r"(sb + 16), "l"(bg + 8));
        asm volatile("cp.async.commit_group;\n");
    };

    const int nt = ksz >> 5;
    load_stage(0, k0);
    load_stage(1, k0 + 32);
    asm volatile("cp.async.wait_group 1;\n");
    __syncthreads();

    for (int tt = 0; tt < nt; tt++) {
        const int buf = tt % 3;
        #pragma unroll
        for (int kp = 0; kp < 2; kp++) {
            unsigned a[4][4], b[4][2];
            #pragma unroll
            for (int mi = 0; mi < 4; mi++) {
                unsigned ad = (unsigned)__cvta_generic_to_shared(
                    &sA[(buf * 128 + wm + mi * 16 + (lane & 15)) * 40 + kp * 16 + ((lane >> 4) << 3)]);
                asm volatile("ldmatrix.sync.aligned.m8n8.x4.shared.b16 {%0,%1,%2,%3}, [%4];\n"
                             : "=r"(a[mi][0]), "=r"(a[mi][1]), "=r"(a[mi][2]), "=r"(a[mi][3])
                             : "r"(ad));
            }
            #pragma unroll
            for (int ni = 0; ni < 4; ni++) {
                unsigned bd = (unsigned)__cvta_generic_to_shared(
                    &sB[(buf * 32 + kp * 16 + (lane & 15)) * 136 + wn + ni * 8]);
                asm volatile("ldmatrix.sync.aligned.m8n8.x2.trans.shared.b16 {%0,%1}, [%2];\n"
                             : "=r"(b[ni][0]), "=r"(b[ni][1]) : "r"(bd));
            }
            #pragma unroll
            for (int mi = 0; mi < 4; mi++)
                #pragma unroll
                for (int ni = 0; ni < 4; ni++)
                    asm volatile(
                        "mma.sync.aligned.m16n8k16.row.col.f32.f16.f16.f32 "
                        "{%0,%1,%2,%3}, {%4,%5,%6,%7}, {%8,%9}, {%0,%1,%2,%3};\n"
                        : "+f"(c[mi][ni][0]), "+f"(c[mi][ni][1]),
                          "+f"(c[mi][ni][2]), "+f"(c[mi][ni][3])
                        : "r"(a[mi][0]), "r"(a[mi][1]), "r"(a[mi][2]), "r"(a[mi][3]),
                          "r"(b[ni][0]), "r"(b[ni][1]));
        }
        if (tt + 2 < nt) {
            load_stage((tt + 2) % 3, k0 + ((tt + 2) << 5));
            asm volatile("cp.async.wait_group 1;\n");
        } else {
            asm volatile("cp.async.wait_group 0;\n");
        }
        __syncthreads();
    }

    const int g = lane >> 2;
    const int t = lane & 3;
    float* Cp = Cpart + (size_t)blockIdx.z * M * Nc;
    #pragma unroll
    for (int mi = 0; mi < 4; mi++) {
        #pragma unroll
        for (int half = 0; half < 2; half++) {
            const int gm = row0 + wm + mi * 16 + g + half * 8;
            if (gm >= M) continue;
            float* Crow = Cp + (size_t)gm * Nc;
            #pragma unroll
            for (int ni = 0; ni < 4; ni++) {
                const int gn = col0 + wn + ni * 8 + 2 * t;
                float2 v;
                v.x = c[mi][ni][half * 2];
                v.y = c[mi][ni][half * 2 + 1];
                *(float2*)&Crow[gn] = v;
            }
        }
    }
}

// classifier split-4 reduce (+bias)
__global__ void reduce4(const float* __restrict__ part, float* __restrict__ out,
                        const float* __restrict__ bias, float scale, int M, int Nc) {
    int i = blockIdx.x * blockDim.x + threadIdx.x;
    if (i >= M * Nc) return;
    size_t st = (size_t)M * Nc;
    float v = part[i] + part[i + st] + part[i + 2 * st] + part[i + 3 * st];
    v *= scale;
    if (bias) v += bias[i % Nc];
    out[i] = v;
}

// layer-1 split-2 reduce fused with BN stats (streaming; 440 blocks)
__global__ void reduce2_bn(const float* __restrict__ part, float* __restrict__ out,
                           const float* __restrict__ bias, float scale, int statoff) {
    int t = threadIdx.x;
    int nper = (NN + gridDim.x - 1) / gridDim.x;
    int r0 = blockIdx.x * nper;
    int r1 = min(NN, r0 + nper);
    const size_t st = (size_t)NN * HID;
    float b = bias[t];
    float s = 0.f, s2 = 0.f;
    for (int r = r0; r < r1; r++) {
        size_t i = (size_t)r * HID + t;
        float v = part[i] + part[i + st];
        v = v * scale + b;
        out[i] = v;
        s += v;
        s2 += v * v;
    }
    atomicAdd(&d_bnstat[statoff + t], s);
    atomicAdd(&d_bnstat[statoff + t + HID], s2);
}

// layer-0 split-2 reduce fused with attention scores (block = row)
__global__ void reduce2_scores(const float* __restrict__ part, float* __restrict__ out,
                               const float* __restrict__ as0, const float* __restrict__ ad0) {
    int row = blockIdx.x;
    int t = threadIdx.x;
    int i = row * HID + t;
    const size_t st = (size_t)NN * HID;
    float v = part[i] + part[i + st];
    out[i] = v;
    int head = t >> 5, lane = t & 31;
    float ss = v * as0[t];
    float sd = v * ad0[t];
    #pragma unroll
    for (int o = 16; o > 0; o >>= 1) {
        ss += __shfl_xor_sync(0xffffffffu, ss, o);
        sd += __shfl_xor_sync(0xffffffffu, sd, o);
    }
    if (lane == 0) {
        d_ss[row * NHEAD + head] = ss;
        d_sd[row * NHEAD + head] = sd;
    }
}

// ---------------- host launcher ----------------
extern "C" void kernel_launch(void* const* d_in, const int* in_sizes, int n_in,
                              void* d_out, int out_size) {
    (void)in_sizes; (void)n_in; (void)out_size;
    const float* x   = (const float*)d_in[0];
    const int*   ei  = (const int*)d_in[1];
    const float* W0  = (const float*)d_in[2];
    const float* as0 = (const float*)d_in[3];
    const float* ad0 = (const float*)d_in[4];
    const float* b0  = (const float*)d_in[5];
    const float* g0  = (const float*)d_in[6];
    const float* be0 = (const float*)d_in[7];
    const float* W1  = (const float*)d_in[8];
    const float* as1 = (const float*)d_in[9];
    const float* ad1 = (const float*)d_in[10];
    const float* b1  = (const float*)d_in[11];
    const float* g1  = (const float*)d_in[12];
    const float* be1 = (const float*)d_in[13];
    const float* Wc  = (const float*)d_in[14];
    const float* bc  = (const float*)d_in[15];
    float* out = (float*)d_out;
    const int* srcp = ei;
    const int* dstp = ei + EIN;

    static int smem_set = 0;
    if (!smem_set) {
        cudaFuncSetAttribute(gemm_f16, cudaFuncAttributeMaxDynamicSharedMemorySize, GF16_SMEM);
        smem_set = 1;
    }

    void *p_counts;
    void *p_h0, *p_hin, *p_xh, *p_w0h, *p_aggh, *p_w1h, *p_part, *p_h2, *p_out0, *p_out1;
    cudaGetSymbolAddress(&p_counts, d_counts);
    cudaGetSymbolAddress(&p_h0,   d_h0);
    cudaGetSymbolAddress(&p_hin,  d_hin);
    cudaGetSymbolAddress(&p_xh,   d_xh);
    cudaGetSymbolAddress(&p_w0h,  d_w0h);
    cudaGetSymbolAddress(&p_aggh, d_aggh);
    cudaGetSymbolAddress(&p_w1h,  d_w1h);
    cudaGetSymbolAddress(&p_part, d_part);
    cudaGetSymbolAddress(&p_h2,   d_h2);
    cudaGetSymbolAddress(&p_out0, d_out0);
    cudaGetSymbolAddress(&p_out1, d_out1);
    float*  h0   = (float*)p_h0;
    float*  hin  = (float*)p_hin;
    __half* xh   = (__half*)p_xh;
    __half* w0h  = (__half*)p_w0h;
    __half* aggh = (__half*)p_aggh;
    __half* w1h  = (__half*)p_w1h;
    float*  part = (float*)p_part;
    float*  h2   = (float*)p_h2;
    float*  out0 = (float*)p_out0;
    float*  out1 = (float*)p_out1;

    // ---- CSR build + precomputes ----
    cudaMemsetAsync(p_counts, 0, (NN + 1) * sizeof(int));
    count_kernel<<<(ETOT + 255) / 256, 256>>>(dstp);
    scan_kernel<<<1, 1024>>>();
    place_kernel<<<(ETOT + 255) / 256, 256>>>(srcp, dstp);
    prep_kernel<<<(PREP_N1 + PREP_N2 + PREP_N3 + 255) / 256, 256>>>(x, W0, W1, as1, ad1);

    // ---- layer 0 (split-K=2) ----
    gemm_f16<<<dim3(HID / 128, (NN + 127) / 128, 2), 256, GF16_SMEM>>>(xh, w0h, part, NN, HID,
                                                                       HID, HID / 2);
    reduce2_scores<<<NN, HID>>>(part, h0, as0, ad0);
    edge_softmax<<<(NN + 3) / 4, 128>>>();
    aggregate_c32<<<NN, 128>>>(h0, b0, out0);
    bn_partial<<<128, HID>>>(out0, 0);
    bn_apply_scores<<<NN, HID>>>(out0, g0, be0, hin, 0);

    // ---- layer 1 (split-K=2) ----
    edge_softmax<<<(NN + 3) / 4, 128>>>();
    aggregate8<<<NN, 128>>>(hin);
    gemm_f16<<<dim3(HID / 128, (NN + 127) / 128, 2), 256, GF16_SMEM>>>(aggh, w1h, part, NN, HID,
                                                                       KBIG, KBIG / 2);
    reduce2_bn<<<440, HID>>>(part, out1, b1, 1.f / NHEAD, 2 * HID);
    bn_apply<<<(NN * HID + 255) / 256, 256>>>(out1, g1, be1, hin, h2, 2 * HID);

    // ---- classifier (exact f32x2, split-4) ----
    gemm128s<<<dim3(1, (NN + 127) / 128, 4), 256>>>(h2, Wc, part, NN, 40, HID, HID / 4);
    reduce4<<<(NN * 40 + 255) / 256, 256>>>(part, out, bc, 1.f, NN, 40);
}